// round 4
// baseline (speedup 1.0000x reference)
#include <cuda_runtime.h>
#include <math.h>
#include <stdint.h>

#define S_TOK 110592   // 48*48*48

typedef unsigned long long ull;

// ---------------- scratch (device globals; no allocation) ----------------
__device__ float g_xw  [S_TOK * 96];   // LN1'd activations, window-ordered
__device__ float g_xT  [S_TOK * 96];   // raw x, token-major
__device__ float g_qkv [S_TOK * 288];  // window-ordered
__device__ float g_attn[S_TOK * 96];   // attention out, window-ordered
__device__ float g_h1  [S_TOK * 96];   // residual-1, token-major
__device__ float g_hn  [S_TOK * 96];   // LN2 output, token-major
// transposed weights (k-contiguous rows), filled by prep kernel each launch
__device__ float g_wqkvT[288 * 96];
__device__ float g_woutT[96 * 96];
__device__ float g_w1T  [384 * 96];
__device__ float g_w2T  [96 * 384];

// ---------------- helpers ----------------
__device__ __forceinline__ float gelu_exact(float v) {
    return 0.5f * v * (1.0f + erff(v * 0.70710678118654752440f));
}
__device__ __forceinline__ void mma_tf32(float* d, const float* a, const float* b) {
    const uint32_t* A = (const uint32_t*)a;
    const uint32_t* B = (const uint32_t*)b;
    asm("mma.sync.aligned.m16n8k8.row.col.f32.tf32.tf32.f32 "
        "{%0,%1,%2,%3}, {%4,%5,%6,%7}, {%8,%9}, {%0,%1,%2,%3};"
        : "+f"(d[0]), "+f"(d[1]), "+f"(d[2]), "+f"(d[3])
        : "r"(A[0]), "r"(A[1]), "r"(A[2]), "r"(A[3]), "r"(B[0]), "r"(B[1]));
}
__device__ __forceinline__ unsigned sptr(const void* p) {
    return (unsigned)__cvta_generic_to_shared(p);
}
__device__ __forceinline__ void ldsm4(float* r, unsigned a) {
    uint32_t* R = (uint32_t*)r;
    asm volatile("ldmatrix.sync.aligned.m8n8.x4.shared.b16 {%0,%1,%2,%3}, [%4];"
        : "=r"(R[0]), "=r"(R[1]), "=r"(R[2]), "=r"(R[3]) : "r"(a));
}
__device__ __forceinline__ void ldsm2(float* r, unsigned a) {
    uint32_t* R = (uint32_t*)r;
    asm volatile("ldmatrix.sync.aligned.m8n8.x2.shared.b16 {%0,%1}, [%2];"
        : "=r"(R[0]), "=r"(R[1]) : "r"(a));
}
__device__ __forceinline__ ull fma2(ull a, ull b, ull c) {
    ull d; asm("fma.rn.f32x2 %0, %1, %2, %3;" : "=l"(d) : "l"(a), "l"(b), "l"(c));
    return d;
}
__device__ __forceinline__ ull pack2(float lo, float hi) {
    ull d; asm("mov.b64 %0, {%1, %2};" : "=l"(d) : "f"(lo), "f"(hi));
    return d;
}
__device__ __forceinline__ float2 unpack2(ull v) {
    float lo, hi; asm("mov.b64 {%0, %1}, %2;" : "=f"(lo), "=f"(hi) : "l"(v));
    return make_float2(lo, hi);
}
__device__ __forceinline__ void cp16(float* dst, const float* src) {
    unsigned d = (unsigned)__cvta_generic_to_shared(dst);
    asm volatile("cp.async.cg.shared.global [%0], [%1], 16;\n" :: "r"(d), "l"(src));
}
__device__ __forceinline__ void cp_commit() { asm volatile("cp.async.commit_group;\n"); }
template<int N> __device__ __forceinline__ void cp_wait() {
    asm volatile("cp.async.wait_group %0;\n" :: "n"(N));
}
__device__ __forceinline__ int wt_to_s(int gr) {
    int wiw = gr / 216, ti = gr - wiw * 216;
    int nd = wiw >> 6, nh = (wiw >> 3) & 7, nw = wiw & 7;
    int wd = ti / 36, wh = (ti / 6) % 6, ww = ti % 6;
    return ((nd * 6 + wd) * 48 + (nh * 6 + wh)) * 48 + (nw * 6 + ww);
}

// ---------------- K0: weight transpose  dst[n][k] = src[k][n] ----------------
__global__ void k0_transpose(const float* __restrict__ src, float* __restrict__ dst,
                             int K, int N) {
    __shared__ float t[32][33];
    int k0 = blockIdx.y * 32, n0 = blockIdx.x * 32;
    int tx = threadIdx.x, ty = threadIdx.y;   // 32 x 8
    #pragma unroll
    for (int i = 0; i < 32; i += 8) {
        int k = k0 + ty + i, n = n0 + tx;
        if (k < K && n < N) t[ty + i][tx] = src[(long)k * N + n];
    }
    __syncthreads();
    #pragma unroll
    for (int i = 0; i < 32; i += 8) {
        int n = n0 + ty + i, k = k0 + tx;
        if (n < N && k < K) dst[(long)n * K + k] = t[tx][ty + i];
    }
}

// ---------------- K1: LN1 + window partition + transpose (coalesced) ----------------
__global__ __launch_bounds__(256) void k1_ln1(const float* __restrict__ x,
                                              const float* __restrict__ gw,
                                              const float* __restrict__ gb) {
    __shared__ float xs[64 * 97];
    __shared__ float smu[64], srs[64];
    __shared__ int srow[64];
    __shared__ float sg[96], sb[96];
    int tid = threadIdx.x;
    int s0 = blockIdx.x * 64;
    if (tid < 96) { sg[tid] = gw[tid]; sb[tid] = gb[tid]; }
    #pragma unroll
    for (int it = 0; it < 24; it++) {
        int i = it * 256 + tid;
        int c = i >> 6, t = i & 63;
        xs[t * 97 + c] = x[(long)c * S_TOK + s0 + t];
    }
    if (tid < 64) {
        int s = s0 + tid;
        int w = s % 48, h = (s / 48) % 48, d = s / 2304;
        int wi = ((d / 6) * 8 + (h / 6)) * 8 + (w / 6);
        int ti = ((d % 6) * 6 + (h % 6)) * 6 + (w % 6);
        srow[tid] = wi * 216 + ti;
    }
    __syncthreads();
    {
        int t = tid >> 2, p = tid & 3;
        float sum = 0.f, sq = 0.f;
        const float* row = &xs[t * 97 + p * 24];
        #pragma unroll
        for (int j = 0; j < 24; j++) { float v = row[j]; sum += v; sq += v * v; }
        sum += __shfl_xor_sync(~0u, sum, 1); sq += __shfl_xor_sync(~0u, sq, 1);
        sum += __shfl_xor_sync(~0u, sum, 2); sq += __shfl_xor_sync(~0u, sq, 2);
        if (p == 0) {
            float mu  = sum * (1.f / 96.f);
            float var = fmaxf(sq * (1.f / 96.f) - mu * mu, 0.f);
            smu[t] = mu;
            srs[t] = rsqrtf(var + 1e-5f);
        }
    }
    __syncthreads();
    #pragma unroll
    for (int it = 0; it < 24; it++) {
        int i = it * 256 + tid;
        int t = i / 96, c = i - t * 96;
        float v = xs[t * 97 + c];
        g_xT[((long)(s0 + t)) * 96 + c] = v;
        g_xw[(long)srow[t] * 96 + c] = (v - smu[t]) * srs[t] * sg[c] + sb[c];
    }
}

// ---------------- tf32 mma GEMM with ldmatrix, BT is [n][k] ----------------
// BM=128, BN=96, BK=32, 256 thr, warps 2(m) x 4(n), warp tile 64x24.
// EPI: 0 plain store, 2 outproj(+bias,+res(g_xT remap)->g_h1, LN2->g_hn)
#define SMEM_GEMM ((2 * 128 * 36 + 2 * 96 * 36) * 4)   // 64512 B
#define CS_LD 101

template<int K, int NB, int EPI>
__global__ __launch_bounds__(256, 2) void mma_gemm(const float* __restrict__ A,
                                                   const float* __restrict__ BT,
                                                   const float* __restrict__ bias,
                                                   float* __restrict__ C,
                                                   const float* __restrict__ lng,
                                                   const float* __restrict__ lnb) {
    extern __shared__ float sm[];
    float* AsBuf[2] = { sm, sm + 128 * 36 };
    float* BsBuf[2] = { sm + 2 * 128 * 36, sm + 2 * 128 * 36 + 96 * 36 };
    float* Cs = sm;
    __shared__ float smu[128], srs[128];
    __shared__ int ssrow[128];

    int tid = threadIdx.x, warp = tid >> 5, lane = tid & 31;
    int wm = warp & 1, wn = warp >> 1;
    int g = lane >> 2, tq = lane & 3;
    long row0 = (long)blockIdx.x * 128;
    int n0 = blockIdx.y * 96;

    int mi = lane >> 3, rr = lane & 7;
    int rowA = wm * 64 + rr + (mi & 1) * 8;
    int colA = (mi >> 1) * 4;
    unsigned aAddr[2] = { sptr(&AsBuf[0][rowA * 36 + colA]),
                          sptr(&AsBuf[1][rowA * 36 + colA]) };
    int rowB = wn * 24 + rr, colB = ((lane >> 3) & 1) * 4;
    unsigned bAddr[2] = { sptr(&BsBuf[0][rowB * 36 + colB]),
                          sptr(&BsBuf[1][rowB * 36 + colB]) };

    int ra = tid >> 3, fa = tid & 7;
    auto issue = [&](int st, int k0) {
        #pragma unroll
        for (int i = 0; i < 4; i++)
            cp16(&AsBuf[st][(ra + 32 * i) * 36 + fa * 4],
                 A + (row0 + ra + 32 * i) * K + k0 + fa * 4);
        #pragma unroll
        for (int i = 0; i < 3; i++) {
            int idx = tid + i * 256;
            int n = idx >> 3, f = idx & 7;
            cp16(&BsBuf[st][n * 36 + f * 4], BT + (long)(n0 + n) * K + k0 + f * 4);
        }
        cp_commit();
    };

    float acc[4][3][4];
    #pragma unroll
    for (int mt = 0; mt < 4; mt++)
        #pragma unroll
        for (int nt = 0; nt < 3; nt++)
            #pragma unroll
            for (int i = 0; i < 4; i++) acc[mt][nt][i] = 0.f;

    constexpr int NK = K / 32;
    issue(0, 0);
    for (int kt = 0; kt < NK; kt++) {
        if (kt + 1 < NK) { issue((kt + 1) & 1, (kt + 1) * 32); cp_wait<1>(); }
        else cp_wait<0>();
        __syncthreads();
        int bp = kt & 1;
        #pragma unroll
        for (int kk = 0; kk < 4; kk++) {
            int kb = kk * 8;
            float af[4][4];
            #pragma unroll
            for (int mt = 0; mt < 4; mt++)
                ldsm4(af[mt], aAddr[bp] + (unsigned)((mt * 16 * 36 + kb) * 4));
            float bf[3][2];
            #pragma unroll
            for (int nt = 0; nt < 3; nt++)
                ldsm2(bf[nt], bAddr[bp] + (unsigned)((nt * 8 * 36 + kb) * 4));
            #pragma unroll
            for (int mt = 0; mt < 4; mt++)
                #pragma unroll
                for (int nt = 0; nt < 3; nt++)
                    mma_tf32(acc[mt][nt], af[mt], bf[nt]);
        }
        __syncthreads();
    }

    if (EPI == 0) {
        #pragma unroll
        for (int mt = 0; mt < 4; mt++) {
            long gr = row0 + wm * 64 + mt * 16 + g;
            #pragma unroll
            for (int nt = 0; nt < 3; nt++) {
                int gc = n0 + wn * 24 + nt * 8 + 2 * tq;
                *(float2*)&C[gr * NB + gc]       = make_float2(acc[mt][nt][0], acc[mt][nt][1]);
                *(float2*)&C[(gr + 8) * NB + gc] = make_float2(acc[mt][nt][2], acc[mt][nt][3]);
            }
        }
    } else {
        if (tid < 128) ssrow[tid] = wt_to_s((int)row0 + tid);
        #pragma unroll
        for (int mt = 0; mt < 4; mt++) {
            int rl = wm * 64 + mt * 16 + g;
            #pragma unroll
            for (int nt = 0; nt < 3; nt++) {
                int c = wn * 24 + nt * 8 + 2 * tq;
                float b0 = bias[c], b1v = bias[c + 1];
                Cs[rl * CS_LD + c]           = acc[mt][nt][0] + b0;
                Cs[rl * CS_LD + c + 1]       = acc[mt][nt][1] + b1v;
                Cs[(rl + 8) * CS_LD + c]     = acc[mt][nt][2] + b0;
                Cs[(rl + 8) * CS_LD + c + 1] = acc[mt][nt][3] + b1v;
            }
        }
        __syncthreads();
        for (int i = tid; i < 128 * 96; i += 256) {
            int r = i / 96, c = i - r * 96;
            int s = ssrow[r];
            float v = Cs[r * CS_LD + c] + g_xT[(long)s * 96 + c];
            Cs[r * CS_LD + c] = v;
            g_h1[(long)s * 96 + c] = v;
        }
        __syncthreads();
        if (tid < 128) {
            float sum = 0.f, sq = 0.f;
            for (int c = 0; c < 96; c++) {
                float v = Cs[tid * CS_LD + c];
                sum += v; sq += v * v;
            }
            float mu  = sum * (1.f / 96.f);
            float var = fmaxf(sq * (1.f / 96.f) - mu * mu, 0.f);
            smu[tid] = mu;
            srs[tid] = rsqrtf(var + 1e-5f);
        }
        __syncthreads();
        for (int i = tid; i < 128 * 96; i += 256) {
            int r = i / 96, c = i - r * 96;
            g_hn[(long)ssrow[r] * 96 + c] =
                (Cs[r * CS_LD + c] - smu[r]) * srs[r] * lng[c] + lnb[c];
        }
    }
}

// ---------------- K5: fused MLP (gelu(hn@W1+b1)@W2 + b2 + res, BM=64) ----------------
// A-tile (64x96) resident; 4 hidden chunks of 96; 24-tile unified cp.async sequence.
#define SMEM_MLP ((64 * 100 + 64 * 100 + 2 * 96 * 36) * 4)   // 78848 B

__global__ __launch_bounds__(256, 2) void k5_mlp(const float* __restrict__ b1,
                                                 const float* __restrict__ b2,
                                                 float* __restrict__ out) {
    extern __shared__ float sm[];
    float* Afull = sm;                     // 64*100
    float* Hs    = sm + 6400;              // 64*100
    float* BsBuf[2] = { sm + 12800, sm + 12800 + 96 * 36 };

    int tid = threadIdx.x, warp = tid >> 5, lane = tid & 31;
    int wm = warp & 1, wn = warp >> 5 ? 0 : warp >> 1;  // placeholder fix below
    wn = warp >> 1;
    int g = lane >> 2, tq = lane & 3;
    long row0 = (long)blockIdx.x * 64;

    int mi = lane >> 3, rr = lane & 7;
    int rowA = wm * 32 + rr + (mi & 1) * 8;
    int colA = (mi >> 1) * 4;
    unsigned aF = sptr(&Afull[rowA * 100 + colA]);
    unsigned aH = sptr(&Hs[rowA * 100 + colA]);
    int rowB = wn * 24 + rr, colB = ((lane >> 3) & 1) * 4;
    unsigned bAddr[2] = { sptr(&BsBuf[0][rowB * 36 + colB]),
                          sptr(&BsBuf[1][rowB * 36 + colB]) };

    auto issueB1 = [&](int st, int c, int k0) {
        #pragma unroll
        for (int i = 0; i < 3; i++) {
            int idx = tid + i * 256;
            int n = idx >> 3, f = idx & 7;
            cp16(&BsBuf[st][n * 36 + f * 4], g_w1T + (long)(c * 96 + n) * 96 + k0 + f * 4);
        }
        cp_commit();
    };
    auto issueB2 = [&](int st, int c, int k0) {
        #pragma unroll
        for (int i = 0; i < 3; i++) {
            int idx = tid + i * 256;
            int n = idx >> 3, f = idx & 7;
            cp16(&BsBuf[st][n * 36 + f * 4], g_w2T + (long)n * 384 + c * 96 + k0 + f * 4);
        }
        cp_commit();
    };
    auto issueT = [&](int t) {
        int c = t / 6, p = (t % 6) / 3, k0 = (t % 3) * 32, st = t & 1;
        if (p == 0) issueB1(st, c, k0); else issueB2(st, c, k0);
    };

    // prologue: Afull + tile0(B1 c0 k0 -> buf0) as ONE group
    #pragma unroll
    for (int i = 0; i < 6; i++) {
        int idx = tid + i * 256;
        int r = idx / 24, f = idx % 24;
        cp16(&Afull[r * 100 + f * 4], &g_hn[(row0 + r) * 96 + f * 4]);
    }
    #pragma unroll
    for (int i = 0; i < 3; i++) {
        int idx = tid + i * 256;
        int n = idx >> 3, f = idx & 7;
        cp16(&BsBuf[0][n * 36 + f * 4], g_w1T + (long)n * 96 + f * 4);
    }
    cp_commit();

    float acc1[2][3][4], accO[2][3][4];
    #pragma unroll
    for (int mt = 0; mt < 2; mt++)
        #pragma unroll
        for (int nt = 0; nt < 3; nt++)
            #pragma unroll
            for (int i = 0; i < 4; i++) { acc1[mt][nt][i] = 0.f; accO[mt][nt][i] = 0.f; }

    auto mmaTile = [&](float (*acc)[3][4], unsigned aBase, int kt, int bp) {
        #pragma unroll
        for (int kk = 0; kk < 4; kk++) {
            int kb = kk * 8;
            float af[2][4];
            #pragma unroll
            for (int mt = 0; mt < 2; mt++)
                ldsm4(af[mt], aBase + (unsigned)((mt * 16 * 100 + kt * 32 + kb) * 4));
            float bf[3][2];
            #pragma unroll
            for (int nt = 0; nt < 3; nt++)
                ldsm2(bf[nt], bAddr[bp] + (unsigned)((nt * 8 * 36 + kb) * 4));
            #pragma unroll
            for (int mt = 0; mt < 2; mt++)
                #pragma unroll
                for (int nt = 0; nt < 3; nt++)
                    mma_tf32(acc[mt][nt], af[mt], bf[nt]);
        }
    };

    for (int t = 0; t < 24; t++) {
        if (t < 23) { issueT(t + 1); cp_wait<1>(); }
        else cp_wait<0>();
        __syncthreads();
        int kt = t % 3, bp = t & 1, ph = (t % 6) / 3;
        if (ph == 0) mmaTile(acc1, aF, kt, bp);
        else         mmaTile(accO, aH, kt, bp);
        __syncthreads();
        if (t % 6 == 2) {
            int c = t / 6;
            #pragma unroll
            for (int mt = 0; mt < 2; mt++) {
                int r = wm * 32 + mt * 16 + g;
                #pragma unroll
                for (int nt = 0; nt < 3; nt++) {
                    int cl = wn * 24 + nt * 8 + 2 * tq;
                    float b0 = b1[c * 96 + cl], bv = b1[c * 96 + cl + 1];
                    Hs[r * 100 + cl]           = gelu_exact(acc1[mt][nt][0] + b0);
                    Hs[r * 100 + cl + 1]       = gelu_exact(acc1[mt][nt][1] + bv);
                    Hs[(r + 8) * 100 + cl]     = gelu_exact(acc1[mt][nt][2] + b0);
                    Hs[(r + 8) * 100 + cl + 1] = gelu_exact(acc1[mt][nt][3] + bv);
                    acc1[mt][nt][0] = acc1[mt][nt][1] = acc1[mt][nt][2] = acc1[mt][nt][3] = 0.f;
                }
            }
            __syncthreads();
        }
    }

    // epilogue: bias2 -> Afull (done being read), + residual, transposed store
    #pragma unroll
    for (int mt = 0; mt < 2; mt++) {
        int r = wm * 32 + mt * 16 + g;
        #pragma unroll
        for (int nt = 0; nt < 3; nt++) {
            int cl = wn * 24 + nt * 8 + 2 * tq;
            float b0 = b2[cl], bv = b2[cl + 1];
            Afull[r * 100 + cl]           = accO[mt][nt][0] + b0;
            Afull[r * 100 + cl + 1]       = accO[mt][nt][1] + bv;
            Afull[(r + 8) * 100 + cl]     = accO[mt][nt][2] + b0;
            Afull[(r + 8) * 100 + cl + 1] = accO[mt][nt][3] + bv;
        }
    }
    __syncthreads();
    for (int i = tid; i < 64 * 96; i += 256) {
        int r = i / 96, c = i - r * 96;
        Afull[r * 100 + c] += g_h1[(row0 + r) * 96 + c];
    }
    __syncthreads();
    for (int i = tid; i < 64 * 96; i += 256) {
        int c = i >> 6, r = i & 63;
        out[(long)c * S_TOK + row0 + r] = Afull[r * 100 + c];
    }
}

// ---------------- K3: window attention (FFMA2, smem-staged Q/K/V) ----------------
__global__ __launch_bounds__(224) void k3_attn(void) {
    int wi = blockIdx.x, head = blockIdx.y, tid = threadIdx.x;
    extern __shared__ float sm[];
    float4* qs4 = (float4*)sm;
    float4* ks4 = qs4 + 216 * 8;
    float4* vs4 = ks4 + 216 * 8;
    long base = (long)wi * 216 * 288;
    int off_q = head * 32, off_k = 96 + head * 32, off_v = 192 + head * 32;
    for (int e = tid; e < 216 * 8; e += 224) {
        int j = e >> 3, q = e & 7;
        const float* rowp = &g_qkv[base + j * 288];
        qs4[e] = *(const float4*)&rowp[off_q + q * 4];
        ks4[e] = *(const float4*)&rowp[off_k + q * 4];
        vs4[e] = *(const float4*)&rowp[off_v + q * 4];
    }
    __syncthreads();
    if (tid >= 216) return;

    ull qp[16];
    {
        const ull* q8 = (const ull*)(qs4 + tid * 8);
        #pragma unroll
        for (int i = 0; i < 16; i++) qp[i] = q8[i];
    }
    ull z = pack2(0.f, 0.f);
    ull acc[16];
    #pragma unroll
    for (int i = 0; i < 16; i++) acc[i] = z;
    float l = 0.f;

    for (int j = 0; j < 216; j++) {
        const ull* kj = (const ull*)(ks4 + j * 8);
        ull s0 = z, s1 = z;
        #pragma unroll
        for (int i = 0; i < 8; i++) {
            s0 = fma2(qp[2 * i],     kj[2 * i],     s0);
            s1 = fma2(qp[2 * i + 1], kj[2 * i + 1], s1);
        }
        float2 f0 = unpack2(s0), f1 = unpack2(s1);
        float s = ((f0.x + f0.y) + (f1.x + f1.y)) * 0.17677669529663687f;
        float p = __expf(s);   // scores tiny; softmax w/o max-subtract is exact
        l += p;
        ull pp = pack2(p, p);
        const ull* vj = (const ull*)(vs4 + j * 8);
        #pragma unroll
        for (int i = 0; i < 16; i++) acc[i] = fma2(pp, vj[i], acc[i]);
    }
    float inv = 1.f / l;
    float* op = &g_attn[((long)wi * 216 + tid) * 96 + head * 32];
    #pragma unroll
    for (int i = 0; i < 16; i++) {
        float2 r = unpack2(acc[i]);
        op[2 * i]     = r.x * inv;
        op[2 * i + 1] = r.y * inv;
    }
}

// ---------------- launch ----------------
extern "C" void kernel_launch(void* const* d_in, const int* in_sizes, int n_in,
                              void* d_out, int out_size) {
    const float* x    = (const float*)d_in[0];
    const float* l1g  = (const float*)d_in[1];
    const float* l1b  = (const float*)d_in[2];
    const float* wqkv = (const float*)d_in[3];
    const float* wout = (const float*)d_in[4];
    const float* bout = (const float*)d_in[5];
    const float* l2g  = (const float*)d_in[6];
    const float* l2b  = (const float*)d_in[7];
    const float* w1   = (const float*)d_in[8];
    const float* b1   = (const float*)d_in[9];
    const float* w2   = (const float*)d_in[10];
    const float* b2   = (const float*)d_in[11];
    float* out = (float*)d_out;

    cudaFuncSetAttribute(mma_gemm<96, 288, 0>, cudaFuncAttributeMaxDynamicSharedMemorySize, SMEM_GEMM);
    cudaFuncSetAttribute(mma_gemm<96, 96, 2>,  cudaFuncAttributeMaxDynamicSharedMemorySize, SMEM_GEMM);
    cudaFuncSetAttribute(k5_mlp,               cudaFuncAttributeMaxDynamicSharedMemorySize, SMEM_MLP);
    cudaFuncSetAttribute(k3_attn,              cudaFuncAttributeMaxDynamicSharedMemorySize, 82944);

    float *p_xw, *p_qkv, *p_attn;
    float *p_wqkvT, *p_woutT, *p_w1T, *p_w2T;
    cudaGetSymbolAddress((void**)&p_xw,    g_xw);
    cudaGetSymbolAddress((void**)&p_qkv,   g_qkv);
    cudaGetSymbolAddress((void**)&p_attn,  g_attn);
    cudaGetSymbolAddress((void**)&p_wqkvT, g_wqkvT);
    cudaGetSymbolAddress((void**)&p_woutT, g_woutT);
    cudaGetSymbolAddress((void**)&p_w1T,   g_w1T);
    cudaGetSymbolAddress((void**)&p_w2T,   g_w2T);

    dim3 tb(32, 8);
    k0_transpose<<<dim3(9, 3), tb>>>(wqkv, p_wqkvT, 96, 288);   // [96][288] -> [288][96]
    k0_transpose<<<dim3(3, 3), tb>>>(wout, p_woutT, 96, 96);
    k0_transpose<<<dim3(12, 3), tb>>>(w1, p_w1T, 96, 384);      // -> [384][96]
    k0_transpose<<<dim3(3, 12), tb>>>(w2, p_w2T, 384, 96);      // -> [96][384]

    k1_ln1<<<S_TOK / 64, 256>>>(x, l1g, l1b);
    mma_gemm<96, 288, 0><<<dim3(864, 3), 256, SMEM_GEMM>>>(p_xw, p_wqkvT, nullptr, p_qkv, nullptr, nullptr);
    k3_attn<<<dim3(512, 3), 224, 82944>>>();
    mma_gemm<96, 96, 2><<<dim3(864, 1), 256, SMEM_GEMM>>>(p_attn, p_woutT, bout, nullptr, l2g, l2b);
    k5_mlp<<<S_TOK / 64, 256, SMEM_MLP>>>(b1, b2, out);
}

// round 7
// speedup vs baseline: 1.0896x; 1.0896x over previous
#include <cuda_runtime.h>
#include <cuda_bf16.h>
#include <math.h>
#include <stdint.h>

#define S_TOK 110592   // 48*48*48

typedef unsigned long long ull;

// ---------------- scratch (device globals; no allocation) ----------------
__device__ float g_xw  [S_TOK * 96];   // LN1'd activations, window-ordered
__device__ float g_xT  [S_TOK * 96];   // raw x, token-major
__device__ float g_qkv [S_TOK * 288];  // window-ordered
__device__ float g_h1  [S_TOK * 96];   // residual-1, token-major
__device__ float g_hn  [S_TOK * 96];   // LN2 output, token-major
__device__ float g_wqkvT[288 * 96];    // [n][k]
__device__ float g_w1T  [384 * 96];    // [n][k]
__device__ float g_w2T  [96 * 384];    // [n][k]
__device__ unsigned short g_woutTb[96 * 96];  // bf16 [n][k]

// ---------------- helpers ----------------
__device__ __forceinline__ float gelu_exact(float v) {
    return 0.5f * v * (1.0f + erff(v * 0.70710678118654752440f));
}
__device__ __forceinline__ void mma_tf32(float* d, const float* a, const float* b) {
    const uint32_t* A = (const uint32_t*)a;
    const uint32_t* B = (const uint32_t*)b;
    asm("mma.sync.aligned.m16n8k8.row.col.f32.tf32.tf32.f32 "
        "{%0,%1,%2,%3}, {%4,%5,%6,%7}, {%8,%9}, {%0,%1,%2,%3};"
        : "+f"(d[0]), "+f"(d[1]), "+f"(d[2]), "+f"(d[3])
        : "r"(A[0]), "r"(A[1]), "r"(A[2]), "r"(A[3]), "r"(B[0]), "r"(B[1]));
}
__device__ __forceinline__ void mma_bf16(float* d, const uint32_t* A, const uint32_t* B) {
    asm("mma.sync.aligned.m16n8k16.row.col.f32.bf16.bf16.f32 "
        "{%0,%1,%2,%3}, {%4,%5,%6,%7}, {%8,%9}, {%0,%1,%2,%3};"
        : "+f"(d[0]), "+f"(d[1]), "+f"(d[2]), "+f"(d[3])
        : "r"(A[0]), "r"(A[1]), "r"(A[2]), "r"(A[3]), "r"(B[0]), "r"(B[1]));
}
__device__ __forceinline__ unsigned sptr(const void* p) {
    return (unsigned)__cvta_generic_to_shared(p);
}
__device__ __forceinline__ void ldsm4(void* r, unsigned a) {
    uint32_t* R = (uint32_t*)r;
    asm volatile("ldmatrix.sync.aligned.m8n8.x4.shared.b16 {%0,%1,%2,%3}, [%4];"
        : "=r"(R[0]), "=r"(R[1]), "=r"(R[2]), "=r"(R[3]) : "r"(a));
}
__device__ __forceinline__ void ldsm2(void* r, unsigned a) {
    uint32_t* R = (uint32_t*)r;
    asm volatile("ldmatrix.sync.aligned.m8n8.x2.shared.b16 {%0,%1}, [%2];"
        : "=r"(R[0]), "=r"(R[1]) : "r"(a));
}
__device__ __forceinline__ ull fma2(ull a, ull b, ull c) {
    ull d; asm("fma.rn.f32x2 %0, %1, %2, %3;" : "=l"(d) : "l"(a), "l"(b), "l"(c));
    return d;
}
__device__ __forceinline__ ull pack2(float lo, float hi) {
    ull d; asm("mov.b64 %0, {%1, %2};" : "=l"(d) : "f"(lo), "f"(hi));
    return d;
}
__device__ __forceinline__ float2 unpack2(ull v) {
    float lo, hi; asm("mov.b64 {%0, %1}, %2;" : "=f"(lo), "=f"(hi) : "l"(v));
    return make_float2(lo, hi);
}
__device__ __forceinline__ uint32_t bf2pack(float lo, float hi) {
    uint32_t r; asm("cvt.rn.bf16x2.f32 %0, %1, %2;" : "=r"(r) : "f"(hi), "f"(lo));
    return r;
}
__device__ __forceinline__ void cp16(float* dst, const float* src) {
    unsigned d = (unsigned)__cvta_generic_to_shared(dst);
    asm volatile("cp.async.cg.shared.global [%0], [%1], 16;\n" :: "r"(d), "l"(src));
}
__device__ __forceinline__ void cp_commit() { asm volatile("cp.async.commit_group;\n"); }
template<int N> __device__ __forceinline__ void cp_wait() {
    asm volatile("cp.async.wait_group %0;\n" :: "n"(N));
}
__device__ __forceinline__ int wt_to_s(int gr) {
    int wiw = gr / 216, ti = gr - wiw * 216;
    int nd = wiw >> 6, nh = (wiw >> 3) & 7, nw = wiw & 7;
    int wd = ti / 36, wh = (ti / 6) % 6, ww = ti % 6;
    return ((nd * 6 + wd) * 48 + (nh * 6 + wh)) * 48 + (nw * 6 + ww);
}

// ---------------- K0: weight transpose fp32  dst[n][k] = src[k][n] ----------------
__global__ void k0_transpose(const float* __restrict__ src, float* __restrict__ dst,
                             int K, int N) {
    __shared__ float t[32][33];
    int k0 = blockIdx.y * 32, n0 = blockIdx.x * 32;
    int tx = threadIdx.x, ty = threadIdx.y;
    #pragma unroll
    for (int i = 0; i < 32; i += 8) {
        int k = k0 + ty + i, n = n0 + tx;
        if (k < K && n < N) t[ty + i][tx] = src[(long)k * N + n];
    }
    __syncthreads();
    #pragma unroll
    for (int i = 0; i < 32; i += 8) {
        int n = n0 + ty + i, k = k0 + tx;
        if (n < N && k < K) dst[(long)n * K + k] = t[tx][ty + i];
    }
}

// ---------------- K0b: wout -> bf16 transposed ----------------
__global__ void k0b_woutb(const float* __restrict__ w) {
    int i = blockIdx.x * 256 + threadIdx.x;
    if (i < 9216) {
        int n = i / 96, k = i - n * 96;
        __nv_bfloat16 b = __float2bfloat16(w[k * 96 + n]);
        g_woutTb[n * 96 + k] = *(unsigned short*)&b;
    }
}

// ---------------- K1: LN1 + window partition + transpose ----------------
__global__ __launch_bounds__(256) void k1_ln1(const float* __restrict__ x,
                                              const float* __restrict__ gw,
                                              const float* __restrict__ gb) {
    __shared__ float xs[64 * 97];
    __shared__ float smu[64], srs[64];
    __shared__ int srow[64];
    __shared__ float sg[96], sb[96];
    int tid = threadIdx.x;
    int s0 = blockIdx.x * 64;
    if (tid < 96) { sg[tid] = gw[tid]; sb[tid] = gb[tid]; }
    #pragma unroll
    for (int it = 0; it < 24; it++) {
        int i = it * 256 + tid;
        int c = i >> 6, t = i & 63;
        xs[t * 97 + c] = x[(long)c * S_TOK + s0 + t];
    }
    if (tid < 64) {
        int s = s0 + tid;
        int w = s % 48, h = (s / 48) % 48, d = s / 2304;
        int wi = ((d / 6) * 8 + (h / 6)) * 8 + (w / 6);
        int ti = ((d % 6) * 6 + (h % 6)) * 6 + (w % 6);
        srow[tid] = wi * 216 + ti;
    }
    __syncthreads();
    {
        int t = tid >> 2, p = tid & 3;
        float sum = 0.f, sq = 0.f;
        const float* row = &xs[t * 97 + p * 24];
        #pragma unroll
        for (int j = 0; j < 24; j++) { float v = row[j]; sum += v; sq += v * v; }
        sum += __shfl_xor_sync(~0u, sum, 1); sq += __shfl_xor_sync(~0u, sq, 1);
        sum += __shfl_xor_sync(~0u, sum, 2); sq += __shfl_xor_sync(~0u, sq, 2);
        if (p == 0) {
            float mu  = sum * (1.f / 96.f);
            float var = fmaxf(sq * (1.f / 96.f) - mu * mu, 0.f);
            smu[t] = mu;
            srs[t] = rsqrtf(var + 1e-5f);
        }
    }
    __syncthreads();
    #pragma unroll
    for (int it = 0; it < 24; it++) {
        int i = it * 256 + tid;
        int t = i / 96, c = i - t * 96;
        float v = xs[t * 97 + c];
        g_xT[((long)(s0 + t)) * 96 + c] = v;
        g_xw[(long)srow[t] * 96 + c] = (v - smu[t]) * srs[t] * sg[c] + sb[c];
    }
}

// ---------------- K2: QKV GEMM, single-stage full-K=96 ----------------
#define K2_SMEM ((128 * 100 + 96 * 100) * 4)
__global__ __launch_bounds__(256, 2) void k2_qkv(void) {
    extern __shared__ float sm[];
    float* As = sm;            // [128][100]
    float* Bs = sm + 12800;    // [96][100]
    int tid = threadIdx.x, warp = tid >> 5, lane = tid & 31;
    int wm = warp & 1, wn = warp >> 1;
    int g = lane >> 2, tq = lane & 3;
    long row0 = (long)blockIdx.x * 128;
    int n0 = blockIdx.y * 96;

    // A: 128 rows x 24 float4 chunks = 3072 = 12 x 256
    #pragma unroll
    for (int i = 0; i < 12; i++) {
        int idx = tid + i * 256;
        int r = idx / 24, f = idx - r * 24;
        cp16(&As[r * 100 + f * 4], &g_xw[(row0 + r) * 96 + f * 4]);
    }
    // B: 96 rows x 24 chunks = 2304 = 9 x 256
    #pragma unroll
    for (int i = 0; i < 9; i++) {
        int idx = tid + i * 256;
        int n = idx / 24, f = idx - n * 24;
        cp16(&Bs[n * 100 + f * 4], &g_wqkvT[(n0 + n) * 96 + f * 4]);
    }
    cp_commit(); cp_wait<0>();
    __syncthreads();

    int mi = lane >> 3, rr = lane & 7;
    unsigned aAddr = sptr(&As[(wm * 64 + rr + (mi & 1) * 8) * 100 + (mi >> 1) * 4]);
    unsigned bAddr = sptr(&Bs[(wn * 24 + rr) * 100 + ((lane >> 3) & 1) * 4]);

    float acc[4][3][4];
    #pragma unroll
    for (int mt = 0; mt < 4; mt++)
        #pragma unroll
        for (int nt = 0; nt < 3; nt++)
            #pragma unroll
            for (int i = 0; i < 4; i++) acc[mt][nt][i] = 0.f;

    #pragma unroll
    for (int ks = 0; ks < 12; ks++) {
        int kb = ks * 8;
        float af[4][4];
        #pragma unroll
        for (int mt = 0; mt < 4; mt++)
            ldsm4(af[mt], aAddr + (unsigned)((mt * 16 * 100 + kb) * 4));
        float bf[3][2];
        #pragma unroll
        for (int nt = 0; nt < 3; nt++)
            ldsm2(bf[nt], bAddr + (unsigned)((nt * 8 * 100 + kb) * 4));
        #pragma unroll
        for (int mt = 0; mt < 4; mt++)
            #pragma unroll
            for (int nt = 0; nt < 3; nt++)
                mma_tf32(acc[mt][nt], af[mt], bf[nt]);
    }

    #pragma unroll
    for (int mt = 0; mt < 4; mt++) {
        long gr = row0 + wm * 64 + mt * 16 + g;
        #pragma unroll
        for (int nt = 0; nt < 3; nt++) {
            int gc = n0 + wn * 24 + nt * 8 + 2 * tq;
            *(float2*)&g_qkv[gr * 288 + gc]       = make_float2(acc[mt][nt][0], acc[mt][nt][1]);
            *(float2*)&g_qkv[(gr + 8) * 288 + gc] = make_float2(acc[mt][nt][2], acc[mt][nt][3]);
        }
    }
}

// ---------------- K34: attention + outproj + residual + LN2, per window ----------------
// OBF_LD=104 halfwords -> 208-byte row stride (16B-aligned for ldmatrix)
#define OBF_LD 104
#define WS_LD 104
#define K34_SMEM (224 * OBF_LD * 2 + 216 * 8 * 16 * 2)   // 46592 + 55296 = 101888
__global__ __launch_bounds__(256, 2) void k34_attn(const float* __restrict__ bout,
                                                   const float* __restrict__ l2g,
                                                   const float* __restrict__ l2b) {
    extern __shared__ char smc[];
    unsigned short* Obf = (unsigned short*)smc;            // [224][104] bf16
    float4* ks4 = (float4*)(smc + 224 * OBF_LD * 2);        // 216*8
    float4* vs4 = ks4 + 216 * 8;
    unsigned short* Ws = (unsigned short*)(smc + 224 * OBF_LD * 2);  // [96][104] bf16, overlays KV
    __shared__ float ssum[224], ssq[224], smu[224], srs[224];
    __shared__ int ssrow[224];

    int wi = blockIdx.x, tid = threadIdx.x;
    int warp = tid >> 5, lane = tid & 31;
    long base = (long)wi * 216 * 288;

    if (tid < 224) { ssum[tid] = 0.f; ssq[tid] = 0.f; }
    if (tid < 216) ssrow[tid] = wt_to_s(wi * 216 + tid);
    for (int i = tid; i < 8 * OBF_LD / 2; i += 256)
        ((uint32_t*)(Obf + 216 * OBF_LD))[i] = 0;

    // ---- attention: 3 heads sequential ----
    for (int head = 0; head < 3; head++) {
        __syncthreads();
        int off_k = 96 + head * 32, off_v = 192 + head * 32;
        for (int e = tid; e < 216 * 8; e += 256) {
            int j = e >> 3, q = e & 7;
            const float* rowp = &g_qkv[base + j * 288];
            ks4[e] = *(const float4*)&rowp[off_k + q * 4];
            vs4[e] = *(const float4*)&rowp[off_v + q * 4];
        }
        __syncthreads();
        if (tid < 216) {
            ull qp[16];
            const ull* q8 = (const ull*)&g_qkv[base + tid * 288 + head * 32];
            #pragma unroll
            for (int i = 0; i < 16; i++) qp[i] = q8[i];
            ull z = pack2(0.f, 0.f);
            ull acc[16];
            #pragma unroll
            for (int i = 0; i < 16; i++) acc[i] = z;
            float l = 0.f;
            for (int j = 0; j < 216; j++) {
                const ull* kj = (const ull*)(ks4 + j * 8);
                ull s0 = z, s1 = z;
                #pragma unroll
                for (int i = 0; i < 8; i++) {
                    s0 = fma2(qp[2 * i],     kj[2 * i],     s0);
                    s1 = fma2(qp[2 * i + 1], kj[2 * i + 1], s1);
                }
                float2 f0 = unpack2(s0), f1 = unpack2(s1);
                float s = ((f0.x + f0.y) + (f1.x + f1.y)) * 0.17677669529663687f;
                float p = __expf(s);   // tiny scores; softmax w/o max-sub is exact
                l += p;
                ull pp = pack2(p, p);
                const ull* vj = (const ull*)(vs4 + j * 8);
                #pragma unroll
                for (int i = 0; i < 16; i++) acc[i] = fma2(pp, vj[i], acc[i]);
            }
            float inv = 1.f / l;
            uint32_t* op = (uint32_t*)&Obf[tid * OBF_LD + head * 32];
            #pragma unroll
            for (int i = 0; i < 16; i++) {
                float2 r = unpack2(acc[i]);
                op[i] = bf2pack(r.x * inv, r.y * inv);
            }
        }
    }
    __syncthreads();

    // ---- stage Wout bf16 into KV region ----
    {
        const uint32_t* wsrc = (const uint32_t*)g_woutTb;
        uint32_t* wdst = (uint32_t*)Ws;
        for (int i = tid; i < 96 * 48; i += 256) {
            int n = i / 48, j = i - n * 48;
            wdst[n * (WS_LD / 2) + j] = wsrc[i];
        }
    }
    __syncthreads();

    // ---- outproj mma: [224 x 96] = Obf @ WoutT, warps 2m x 4n ----
    int wm = warp & 1, wn = warp >> 1;
    int g = lane >> 2, tq = lane & 3;
    unsigned aAddr = sptr(Obf) +
        (unsigned)(((wm * 112 + (lane & 7) + ((lane >> 3) & 1) * 8) * OBF_LD +
                    ((lane >> 4) & 1) * 8) * 2);
    unsigned bAddr = sptr(Ws) +
        (unsigned)(((wn * 24 + (lane & 7)) * WS_LD + ((lane >> 3) & 1) * 8) * 2);

    float acc[7][3][4];
    #pragma unroll
    for (int mt = 0; mt < 7; mt++)
        #pragma unroll
        for (int nt = 0; nt < 3; nt++)
            #pragma unroll
            for (int i = 0; i < 4; i++) acc[mt][nt][i] = 0.f;

    #pragma unroll
    for (int ks = 0; ks < 6; ks++) {
        uint32_t bf[3][2];
        #pragma unroll
        for (int nt = 0; nt < 3; nt++)
            ldsm2(bf[nt], bAddr + (unsigned)(nt * 8 * WS_LD * 2 + ks * 32));
        #pragma unroll
        for (int mt = 0; mt < 7; mt++) {
            uint32_t af[4];
            ldsm4(af, aAddr + (unsigned)(mt * 16 * OBF_LD * 2 + ks * 32));
            #pragma unroll
            for (int nt = 0; nt < 3; nt++)
                mma_bf16(acc[mt][nt], af, bf[nt]);
        }
    }

    // ---- epilogue: +bias, +residual(g_xT), emit g_h1, LN2 stats ----
    #pragma unroll
    for (int mt = 0; mt < 7; mt++) {
        int r1 = wm * 112 + mt * 16 + g;
        int r2 = r1 + 8;
        float s1 = 0.f, q1 = 0.f, s2 = 0.f, q2 = 0.f;
        int t1 = ssrow[r1];
        int t2 = (r2 < 216) ? ssrow[r2] : 0;
        #pragma unroll
        for (int nt = 0; nt < 3; nt++) {
            int c = wn * 24 + nt * 8 + 2 * tq;
            float b0 = bout[c], b1v = bout[c + 1];
            {
                float2 xr = *(const float2*)&g_xT[(long)t1 * 96 + c];
                float v0 = acc[mt][nt][0] + b0 + xr.x;
                float v1 = acc[mt][nt][1] + b1v + xr.y;
                *(float2*)&g_h1[(long)t1 * 96 + c] = make_float2(v0, v1);
                acc[mt][nt][0] = v0; acc[mt][nt][1] = v1;
                s1 += v0 + v1; q1 += v0 * v0 + v1 * v1;
            }
            if (r2 < 216) {
                float2 xr = *(const float2*)&g_xT[(long)t2 * 96 + c];
                float v2 = acc[mt][nt][2] + b0 + xr.x;
                float v3 = acc[mt][nt][3] + b1v + xr.y;
                *(float2*)&g_h1[(long)t2 * 96 + c] = make_float2(v2, v3);
                acc[mt][nt][2] = v2; acc[mt][nt][3] = v3;
                s2 += v2 + v3; q2 += v2 * v2 + v3 * v3;
            }
        }
        s1 += __shfl_xor_sync(~0u, s1, 1); q1 += __shfl_xor_sync(~0u, q1, 1);
        s1 += __shfl_xor_sync(~0u, s1, 2); q1 += __shfl_xor_sync(~0u, q1, 2);
        s2 += __shfl_xor_sync(~0u, s2, 1); q2 += __shfl_xor_sync(~0u, q2, 1);
        s2 += __shfl_xor_sync(~0u, s2, 2); q2 += __shfl_xor_sync(~0u, q2, 2);
        if (tq == 0) {
            atomicAdd(&ssum[r1], s1); atomicAdd(&ssq[r1], q1);
            if (r2 < 216) { atomicAdd(&ssum[r2], s2); atomicAdd(&ssq[r2], q2); }
        }
    }
    __syncthreads();
    if (tid < 216) {
        float mu  = ssum[tid] * (1.f / 96.f);
        float var = fmaxf(ssq[tid] * (1.f / 96.f) - mu * mu, 0.f);
        smu[tid] = mu;
        srs[tid] = rsqrtf(var + 1e-5f);
    }
    __syncthreads();
    #pragma unroll
    for (int mt = 0; mt < 7; mt++) {
        int r1 = wm * 112 + mt * 16 + g;
        int r2 = r1 + 8;
        float mu1 = smu[r1], rs1 = srs[r1];
        float mu2 = (r2 < 216) ? smu[r2] : 0.f, rs2 = (r2 < 216) ? srs[r2] : 0.f;
        int t1 = ssrow[r1];
        int t2 = (r2 < 216) ? ssrow[r2] : 0;
        #pragma unroll
        for (int nt = 0; nt < 3; nt++) {
            int c = wn * 24 + nt * 8 + 2 * tq;
            float g0 = l2g[c], g1 = l2g[c + 1];
            float bb0 = l2b[c], bb1 = l2b[c + 1];
            {
                float n0 = (acc[mt][nt][0] - mu1) * rs1 * g0 + bb0;
                float n1 = (acc[mt][nt][1] - mu1) * rs1 * g1 + bb1;
                *(float2*)&g_hn[(long)t1 * 96 + c] = make_float2(n0, n1);
            }
            if (r2 < 216) {
                float n2 = (acc[mt][nt][2] - mu2) * rs2 * g0 + bb0;
                float n3 = (acc[mt][nt][3] - mu2) * rs2 * g1 + bb1;
                *(float2*)&g_hn[(long)t2 * 96 + c] = make_float2(n2, n3);
            }
        }
    }
}

// ---------------- K5: fused MLP, single-stage phases, BM=64 ----------------
#define K5_SMEM ((64 * 100 * 2 + 96 * 100) * 4)   // 89600
__global__ __launch_bounds__(256, 2) void k5_mlp(const float* __restrict__ b1,
                                                 const float* __restrict__ b2,
                                                 float* __restrict__ out) {
    extern __shared__ float sm[];
    float* As = sm;            // [64][100]
    float* Hs = sm + 6400;     // [64][100]
    float* Bs = sm + 12800;    // [96][100]
    int tid = threadIdx.x, warp = tid >> 5, lane = tid & 31;
    int wm = warp & 1, wn = warp >> 1;
    int g = lane >> 2, tq = lane & 3;
    long row0 = (long)blockIdx.x * 64;

    auto stageB = [&](const float* src, long rowStride) {
        // 96 rows x 24 chunks = 2304 = 9 x 256
        #pragma unroll
        for (int i = 0; i < 9; i++) {
            int idx = tid + i * 256;
            int n = idx / 24, f = idx - n * 24;
            cp16(&Bs[n * 100 + f * 4], src + n * rowStride + f * 4);
        }
        cp_commit();
    };

    // A: 64 rows x 24 chunks = 1536 = 6 x 256
    #pragma unroll
    for (int i = 0; i < 6; i++) {
        int idx = tid + i * 256;
        int r = idx / 24, f = idx - r * 24;
        cp16(&As[r * 100 + f * 4], &g_hn[(row0 + r) * 96 + f * 4]);
    }
    stageB(g_w1T, 96);
    cp_wait<0>();
    __syncthreads();

    int mi = lane >> 3, rr = lane & 7;
    unsigned aF = sptr(&As[(wm * 32 + rr + (mi & 1) * 8) * 100 + (mi >> 1) * 4]);
    unsigned aH = sptr(&Hs[(wm * 32 + rr + (mi & 1) * 8) * 100 + (mi >> 1) * 4]);
    unsigned bAddr = sptr(&Bs[(wn * 24 + rr) * 100 + ((lane >> 3) & 1) * 4]);

    float accO[2][3][4];
    #pragma unroll
    for (int mt = 0; mt < 2; mt++)
        #pragma unroll
        for (int nt = 0; nt < 3; nt++)
            #pragma unroll
            for (int i = 0; i < 4; i++) accO[mt][nt][i] = 0.f;

    for (int c = 0; c < 4; c++) {
        float acc1[2][3][4];
        #pragma unroll
        for (int mt = 0; mt < 2; mt++)
            #pragma unroll
            for (int nt = 0; nt < 3; nt++)
                #pragma unroll
                for (int i = 0; i < 4; i++) acc1[mt][nt][i] = 0.f;
        #pragma unroll
        for (int ks = 0; ks < 12; ks++) {
            int kb = ks * 8;
            float af[2][4];
            #pragma unroll
            for (int mt = 0; mt < 2; mt++)
                ldsm4(af[mt], aF + (unsigned)((mt * 16 * 100 + kb) * 4));
            float bf[3][2];
            #pragma unroll
            for (int nt = 0; nt < 3; nt++)
                ldsm2(bf[nt], bAddr + (unsigned)((nt * 8 * 100 + kb) * 4));
            #pragma unroll
            for (int mt = 0; mt < 2; mt++)
                #pragma unroll
                for (int nt = 0; nt < 3; nt++)
                    mma_tf32(acc1[mt][nt], af[mt], bf[nt]);
        }
        #pragma unroll
        for (int mt = 0; mt < 2; mt++) {
            int r = wm * 32 + mt * 16 + g;
            #pragma unroll
            for (int nt = 0; nt < 3; nt++) {
                int cl = wn * 24 + nt * 8 + 2 * tq;
                float b0 = b1[c * 96 + cl], bv = b1[c * 96 + cl + 1];
                Hs[r * 100 + cl]           = gelu_exact(acc1[mt][nt][0] + b0);
                Hs[r * 100 + cl + 1]       = gelu_exact(acc1[mt][nt][1] + bv);
                Hs[(r + 8) * 100 + cl]     = gelu_exact(acc1[mt][nt][2] + b0);
                Hs[(r + 8) * 100 + cl + 1] = gelu_exact(acc1[mt][nt][3] + bv);
            }
        }
        __syncthreads();
        stageB(g_w2T + c * 96, 384);
        cp_wait<0>();
        __syncthreads();
        #pragma unroll
        for (int ks = 0; ks < 12; ks++) {
            int kb = ks * 8;
            float af[2][4];
            #pragma unroll
            for (int mt = 0; mt < 2; mt++)
                ldsm4(af[mt], aH + (unsigned)((mt * 16 * 100 + kb) * 4));
            float bf[3][2];
            #pragma unroll
            for (int nt = 0; nt < 3; nt++)
                ldsm2(bf[nt], bAddr + (unsigned)((nt * 8 * 100 + kb) * 4));
            #pragma unroll
            for (int mt = 0; mt < 2; mt++)
                #pragma unroll
                for (int nt = 0; nt < 3; nt++)
                    mma_tf32(accO[mt][nt], af[mt], bf[nt]);
        }
        if (c < 3) {
            __syncthreads();
            stageB(g_w1T + (long)(c + 1) * 96 * 96, 96);
            cp_wait<0>();
            __syncthreads();
        }
    }

    __syncthreads();
    #pragma unroll
    for (int mt = 0; mt < 2; mt++) {
        int r = wm * 32 + mt * 16 + g;
        #pragma unroll
        for (int nt = 0; nt < 3; nt++) {
            int cl = wn * 24 + nt * 8 + 2 * tq;
            float b0 = b2[cl], bv = b2[cl + 1];
            As[r * 100 + cl]           = accO[mt][nt][0] + b0;
            As[r * 100 + cl + 1]       = accO[mt][nt][1] + bv;
            As[(r + 8) * 100 + cl]     = accO[mt][nt][2] + b0;
            As[(r + 8) * 100 + cl + 1] = accO[mt][nt][3] + bv;
        }
    }
    __syncthreads();
    for (int i = tid; i < 64 * 96; i += 256) {
        int r = i / 96, c = i - r * 96;
        As[r * 100 + c] += g_h1[(row0 + r) * 96 + c];
    }
    __syncthreads();
    for (int i = tid; i < 64 * 96; i += 256) {
        int c = i >> 6, r = i & 63;
        out[(long)c * S_TOK + row0 + r] = As[r * 100 + c];
    }
}

// ---------------- launch ----------------
extern "C" void kernel_launch(void* const* d_in, const int* in_sizes, int n_in,
                              void* d_out, int out_size) {
    const float* x    = (const float*)d_in[0];
    const float* l1g  = (const float*)d_in[1];
    const float* l1b  = (const float*)d_in[2];
    const float* wqkv = (const float*)d_in[3];
    const float* wout = (const float*)d_in[4];
    const float* bout = (const float*)d_in[5];
    const float* l2g  = (const float*)d_in[6];
    const float* l2b  = (const float*)d_in[7];
    const float* w1   = (const float*)d_in[8];
    const float* b1   = (const float*)d_in[9];
    const float* w2   = (const float*)d_in[10];
    const float* b2   = (const float*)d_in[11];
    float* out = (float*)d_out;

    cudaFuncSetAttribute(k2_qkv,   cudaFuncAttributeMaxDynamicSharedMemorySize, K2_SMEM);
    cudaFuncSetAttribute(k34_attn, cudaFuncAttributeMaxDynamicSharedMemorySize, K34_SMEM);
    cudaFuncSetAttribute(k5_mlp,   cudaFuncAttributeMaxDynamicSharedMemorySize, K5_SMEM);

    float *p_wqkvT, *p_w1T, *p_w2T;
    cudaGetSymbolAddress((void**)&p_wqkvT, g_wqkvT);
    cudaGetSymbolAddress((void**)&p_w1T,   g_w1T);
    cudaGetSymbolAddress((void**)&p_w2T,   g_w2T);

    dim3 tb(32, 8);
    k0_transpose<<<dim3(9, 3), tb>>>(wqkv, p_wqkvT, 96, 288);
    k0_transpose<<<dim3(12, 3), tb>>>(w1, p_w1T, 96, 384);
    k0_transpose<<<dim3(3, 12), tb>>>(w2, p_w2T, 384, 96);
    k0b_woutb<<<36, 256>>>(wout);

    k1_ln1<<<S_TOK / 64, 256>>>(x, l1g, l1b);
    k2_qkv<<<dim3(864, 3), 256, K2_SMEM>>>();
    k34_attn<<<512, 256, K34_SMEM>>>(bout, l2g, l2b);
    k5_mlp<<<S_TOK / 64, 256, K5_SMEM>>>(b1, b2, out);
}

// round 8
// speedup vs baseline: 1.1348x; 1.0415x over previous
#include <cuda_runtime.h>
#include <cuda_bf16.h>
#include <math.h>
#include <stdint.h>

#define S_TOK 110592   // 48*48*48

typedef unsigned long long ull;

// ---------------- scratch (device globals; no allocation) ----------------
__device__ unsigned short g_xwb[S_TOK * 96];  // LN1'd activations, window-ordered, bf16
__device__ float g_xT  [S_TOK * 96];   // raw x, token-major
__device__ float g_h1  [S_TOK * 96];   // residual-1, token-major
__device__ float g_hn  [S_TOK * 96];   // LN2 output, token-major
__device__ float g_w1T [384 * 96];     // [n][k] fp32
__device__ float g_w2T [96 * 384];     // [n][k] fp32
__device__ unsigned short g_wqkvTb[288 * 96]; // bf16 [n][k]
__device__ unsigned short g_woutTb[96 * 96];  // bf16 [n][k]

// ---------------- helpers ----------------
__device__ __forceinline__ float gelu_exact(float v) {
    return 0.5f * v * (1.0f + erff(v * 0.70710678118654752440f));
}
__device__ __forceinline__ void mma_tf32(float* d, const float* a, const float* b) {
    const uint32_t* A = (const uint32_t*)a;
    const uint32_t* B = (const uint32_t*)b;
    asm("mma.sync.aligned.m16n8k8.row.col.f32.tf32.tf32.f32 "
        "{%0,%1,%2,%3}, {%4,%5,%6,%7}, {%8,%9}, {%0,%1,%2,%3};"
        : "+f"(d[0]), "+f"(d[1]), "+f"(d[2]), "+f"(d[3])
        : "r"(A[0]), "r"(A[1]), "r"(A[2]), "r"(A[3]), "r"(B[0]), "r"(B[1]));
}
__device__ __forceinline__ void mma_bf16(float* d, const uint32_t* A, const uint32_t* B) {
    asm("mma.sync.aligned.m16n8k16.row.col.f32.bf16.bf16.f32 "
        "{%0,%1,%2,%3}, {%4,%5,%6,%7}, {%8,%9}, {%0,%1,%2,%3};"
        : "+f"(d[0]), "+f"(d[1]), "+f"(d[2]), "+f"(d[3])
        : "r"(A[0]), "r"(A[1]), "r"(A[2]), "r"(A[3]), "r"(B[0]), "r"(B[1]));
}
__device__ __forceinline__ unsigned sptr(const void* p) {
    return (unsigned)__cvta_generic_to_shared(p);
}
__device__ __forceinline__ void ldsm4(void* r, unsigned a) {
    uint32_t* R = (uint32_t*)r;
    asm volatile("ldmatrix.sync.aligned.m8n8.x4.shared.b16 {%0,%1,%2,%3}, [%4];"
        : "=r"(R[0]), "=r"(R[1]), "=r"(R[2]), "=r"(R[3]) : "r"(a));
}
__device__ __forceinline__ void ldsm2(void* r, unsigned a) {
    uint32_t* R = (uint32_t*)r;
    asm volatile("ldmatrix.sync.aligned.m8n8.x2.shared.b16 {%0,%1}, [%2];"
        : "=r"(R[0]), "=r"(R[1]) : "r"(a));
}
__device__ __forceinline__ ull fma2(ull a, ull b, ull c) {
    ull d; asm("fma.rn.f32x2 %0, %1, %2, %3;" : "=l"(d) : "l"(a), "l"(b), "l"(c));
    return d;
}
__device__ __forceinline__ ull pack2(float lo, float hi) {
    ull d; asm("mov.b64 %0, {%1, %2};" : "=l"(d) : "f"(lo), "f"(hi));
    return d;
}
__device__ __forceinline__ float2 unpack2(ull v) {
    float lo, hi; asm("mov.b64 {%0, %1}, %2;" : "=f"(lo), "=f"(hi) : "l"(v));
    return make_float2(lo, hi);
}
__device__ __forceinline__ uint32_t bf2pack(float lo, float hi) {
    uint32_t r; asm("cvt.rn.bf16x2.f32 %0, %1, %2;" : "=r"(r) : "f"(hi), "f"(lo));
    return r;
}
__device__ __forceinline__ void cp16(void* dst, const void* src) {
    unsigned d = (unsigned)__cvta_generic_to_shared(dst);
    asm volatile("cp.async.cg.shared.global [%0], [%1], 16;\n" :: "r"(d), "l"(src));
}
__device__ __forceinline__ void cp_commit() { asm volatile("cp.async.commit_group;\n"); }
template<int N> __device__ __forceinline__ void cp_wait() {
    asm volatile("cp.async.wait_group %0;\n" :: "n"(N));
}
__device__ __forceinline__ int wt_to_s(int gr) {
    int wiw = gr / 216, ti = gr - wiw * 216;
    int nd = wiw >> 6, nh = (wiw >> 3) & 7, nw = wiw & 7;
    int wd = ti / 36, wh = (ti / 6) % 6, ww = ti % 6;
    return ((nd * 6 + wd) * 48 + (nh * 6 + wh)) * 48 + (nw * 6 + ww);
}

// ---------------- K0: weight transpose fp32  dst[n][k] = src[k][n] ----------------
__global__ void k0_transpose(const float* __restrict__ src, float* __restrict__ dst,
                             int K, int N) {
    __shared__ float t[32][33];
    int k0 = blockIdx.y * 32, n0 = blockIdx.x * 32;
    int tx = threadIdx.x, ty = threadIdx.y;
    #pragma unroll
    for (int i = 0; i < 32; i += 8) {
        int k = k0 + ty + i, n = n0 + tx;
        if (k < K && n < N) t[ty + i][tx] = src[(long)k * N + n];
    }
    __syncthreads();
    #pragma unroll
    for (int i = 0; i < 32; i += 8) {
        int n = n0 + ty + i, k = k0 + tx;
        if (n < N && k < K) dst[(long)n * K + k] = t[tx][ty + i];
    }
}

// ---------------- K0q: wqkv -> bf16 transposed [288][96] ----------------
__global__ void k0q_wqkvb(const float* __restrict__ w) {
    int i = blockIdx.x * 256 + threadIdx.x;
    if (i < 288 * 96) {
        int n = i / 96, k = i - n * 96;
        __nv_bfloat16 b = __float2bfloat16(w[k * 288 + n]);
        g_wqkvTb[n * 96 + k] = *(unsigned short*)&b;
    }
}

// ---------------- K0b: wout -> bf16 transposed ----------------
__global__ void k0b_woutb(const float* __restrict__ w) {
    int i = blockIdx.x * 256 + threadIdx.x;
    if (i < 9216) {
        int n = i / 96, k = i - n * 96;
        __nv_bfloat16 b = __float2bfloat16(w[k * 96 + n]);
        g_woutTb[n * 96 + k] = *(unsigned short*)&b;
    }
}

// ---------------- K1: LN1 + window partition (bf16) + transpose ----------------
__global__ __launch_bounds__(256) void k1_ln1(const float* __restrict__ x,
                                              const float* __restrict__ gw,
                                              const float* __restrict__ gb) {
    __shared__ float xs[64 * 97];
    __shared__ float smu[64], srs[64];
    __shared__ int srow[64];
    __shared__ float sg[96], sb[96];
    int tid = threadIdx.x;
    int s0 = blockIdx.x * 64;
    if (tid < 96) { sg[tid] = gw[tid]; sb[tid] = gb[tid]; }
    #pragma unroll
    for (int it = 0; it < 24; it++) {
        int i = it * 256 + tid;
        int c = i >> 6, t = i & 63;
        xs[t * 97 + c] = x[(long)c * S_TOK + s0 + t];
    }
    if (tid < 64) {
        int s = s0 + tid;
        int w = s % 48, h = (s / 48) % 48, d = s / 2304;
        int wi = ((d / 6) * 8 + (h / 6)) * 8 + (w / 6);
        int ti = ((d % 6) * 6 + (h % 6)) * 6 + (w % 6);
        srow[tid] = wi * 216 + ti;
    }
    __syncthreads();
    {
        int t = tid >> 2, p = tid & 3;
        float sum = 0.f, sq = 0.f;
        const float* row = &xs[t * 97 + p * 24];
        #pragma unroll
        for (int j = 0; j < 24; j++) { float v = row[j]; sum += v; sq += v * v; }
        sum += __shfl_xor_sync(~0u, sum, 1); sq += __shfl_xor_sync(~0u, sq, 1);
        sum += __shfl_xor_sync(~0u, sum, 2); sq += __shfl_xor_sync(~0u, sq, 2);
        if (p == 0) {
            float mu  = sum * (1.f / 96.f);
            float var = fmaxf(sq * (1.f / 96.f) - mu * mu, 0.f);
            smu[t] = mu;
            srs[t] = rsqrtf(var + 1e-5f);
        }
    }
    __syncthreads();
    // raw x token-major (fp32)
    #pragma unroll
    for (int it = 0; it < 24; it++) {
        int i = it * 256 + tid;
        int t = i / 96, c = i - t * 96;
        g_xT[((long)(s0 + t)) * 96 + c] = xs[t * 97 + c];
    }
    // LN1'd, window-ordered, bf16-packed
    #pragma unroll
    for (int it = 0; it < 12; it++) {
        int i = it * 256 + tid;       // < 3072 = 64*48
        int t = i / 48, c2 = (i - t * 48) * 2;
        float v0 = (xs[t * 97 + c2]     - smu[t]) * srs[t] * sg[c2]     + sb[c2];
        float v1 = (xs[t * 97 + c2 + 1] - smu[t]) * srs[t] * sg[c2 + 1] + sb[c2 + 1];
        ((uint32_t*)g_xwb)[(long)srow[t] * 48 + c2 / 2] = bf2pack(v0, v1);
    }
}

// ---------------- K34: LN1'd-x -> QKV -> attention -> outproj -> res -> LN2 ----------------
// smem (bytes): Asb[224][104]bf16 @0, Obf[224][104]bf16 @46592, Wq[96][104]bf16 @93184,
//               Qs[216][34]f32 @113152, Ks[216][32]f32 @142528, Vs[216][32]f32 @170176
#define AB_LD 104
#define K34_SMEM 197824
__global__ __launch_bounds__(256, 1) void k34_attn(const float* __restrict__ bout,
                                                   const float* __restrict__ l2g,
                                                   const float* __restrict__ l2b) {
    extern __shared__ char smc[];
    unsigned short* Asb = (unsigned short*)smc;
    unsigned short* Obf = (unsigned short*)(smc + 46592);
    unsigned short* Wq  = (unsigned short*)(smc + 93184);
    float* Qs = (float*)(smc + 113152);   // [216][34]
    float* Ks = (float*)(smc + 142528);   // [216][32]
    float* Vs = (float*)(smc + 170176);   // [216][32]
    __shared__ float ssum[224], ssq[224], smu[224], srs[224];
    __shared__ int ssrow[224];

    int wi = blockIdx.x, tid = threadIdx.x;
    int warp = tid >> 5, lane = tid & 31;
    int wm = warp & 1, wn = warp >> 1;
    int g = lane >> 2, tq = lane & 3;
    int rr = lane & 7;

    if (tid < 224) { ssum[tid] = 0.f; ssq[tid] = 0.f; }
    if (tid < 216) ssrow[tid] = wt_to_s(wi * 216 + tid);
    // zero pad rows 216..223 of Asb and Obf
    for (int i = tid; i < 416; i += 256) {
        ((uint32_t*)(Asb + 216 * AB_LD))[i] = 0;
        ((uint32_t*)(Obf + 216 * AB_LD))[i] = 0;
    }

    // stage xw tile: 216 rows x 12 x16B chunks (bf16)
    const unsigned short* xsrc = g_xwb + (long)wi * 216 * 96;
    for (int i = tid; i < 2592; i += 256) {
        int r = i / 12, f = i - r * 12;
        cp16(Asb + r * AB_LD + f * 8, xsrc + r * 96 + f * 8);
    }
    cp_commit();

    // fragment addresses (shared by QKV mma and outproj mma)
    unsigned aAsb = sptr(Asb) +
        (unsigned)(((wm * 112 + rr + ((lane >> 3) & 1) * 8) * AB_LD +
                    ((lane >> 4) & 1) * 8) * 2);
    unsigned aObf = sptr(Obf) +
        (unsigned)(((wm * 112 + rr + ((lane >> 3) & 1) * 8) * AB_LD +
                    ((lane >> 4) & 1) * 8) * 2);
    unsigned bW = sptr(Wq) +
        (unsigned)(((wn * 24 + rr) * AB_LD + ((lane >> 3) & 1) * 8) * 2);

    // ---- per head: stage W slice, QKV mma, attention ----
    for (int head = 0; head < 3; head++) {
        // stage Wq rows: n<32 -> q col, 32..63 -> k col, 64..95 -> v col
        for (int i = tid; i < 1152; i += 256) {
            int n = i / 12, f = i - n * 12;
            int src = (n < 32) ? (head * 32 + n)
                    : (n < 64) ? (96 + head * 32 + n - 32)
                               : (192 + head * 32 + n - 64);
            cp16(Wq + n * AB_LD + f * 8, g_wqkvTb + src * 96 + f * 8);
        }
        cp_commit(); cp_wait<0>();
        __syncthreads();   // W + (head0: Asb) ready; prev attention done

        // QKV mma: [224x96] = Asb @ Wq^T
        float acc[7][3][4];
        #pragma unroll
        for (int mt = 0; mt < 7; mt++)
            #pragma unroll
            for (int nt = 0; nt < 3; nt++)
                #pragma unroll
                for (int i = 0; i < 4; i++) acc[mt][nt][i] = 0.f;
        #pragma unroll
        for (int ks = 0; ks < 6; ks++) {
            uint32_t bf[3][2];
            #pragma unroll
            for (int nt = 0; nt < 3; nt++)
                ldsm2(bf[nt], bW + (unsigned)(nt * 8 * AB_LD * 2 + ks * 32));
            #pragma unroll
            for (int mt = 0; mt < 7; mt++) {
                uint32_t af[4];
                ldsm4(af, aAsb + (unsigned)(mt * 16 * AB_LD * 2 + ks * 32));
                #pragma unroll
                for (int nt = 0; nt < 3; nt++)
                    mma_bf16(acc[mt][nt], af, bf[nt]);
            }
        }
        // scatter Q/K/V to fp32 smem
        #pragma unroll
        for (int mt = 0; mt < 7; mt++) {
            int r1 = wm * 112 + mt * 16 + g;
            int r2 = r1 + 8;
            #pragma unroll
            for (int nt = 0; nt < 3; nt++) {
                int c = wn * 24 + nt * 8 + 2 * tq;
                float2 v1 = make_float2(acc[mt][nt][0], acc[mt][nt][1]);
                float2 v2 = make_float2(acc[mt][nt][2], acc[mt][nt][3]);
                if (c < 32) {
                    *(float2*)&Qs[r1 * 34 + c] = v1;
                    if (r2 < 216) *(float2*)&Qs[r2 * 34 + c] = v2;
                } else if (c < 64) {
                    *(float2*)&Ks[r1 * 32 + c - 32] = v1;
                    if (r2 < 216) *(float2*)&Ks[r2 * 32 + c - 32] = v2;
                } else {
                    *(float2*)&Vs[r1 * 32 + c - 64] = v1;
                    if (r2 < 216) *(float2*)&Vs[r2 * 32 + c - 64] = v2;
                }
            }
        }
        __syncthreads();   // Q/K/V ready

        // attention (one query row per thread)
        if (tid < 216) {
            ull qp[16];
            const ull* q8 = (const ull*)&Qs[tid * 34];
            #pragma unroll
            for (int i = 0; i < 16; i++) qp[i] = q8[i];
            ull z = pack2(0.f, 0.f);
            ull oacc[16];
            #pragma unroll
            for (int i = 0; i < 16; i++) oacc[i] = z;
            float l = 0.f;
            for (int j = 0; j < 216; j++) {
                const ull* kj = (const ull*)&Ks[j * 32];
                ull s0 = z, s1 = z;
                #pragma unroll
                for (int i = 0; i < 8; i++) {
                    s0 = fma2(qp[2 * i],     kj[2 * i],     s0);
                    s1 = fma2(qp[2 * i + 1], kj[2 * i + 1], s1);
                }
                float2 f0 = unpack2(s0), f1 = unpack2(s1);
                float s = ((f0.x + f0.y) + (f1.x + f1.y)) * 0.17677669529663687f;
                float p = __expf(s);   // tiny scores; softmax w/o max-sub is exact
                l += p;
                ull pp = pack2(p, p);
                const ull* vj = (const ull*)&Vs[j * 32];
                #pragma unroll
                for (int i = 0; i < 16; i++) oacc[i] = fma2(pp, vj[i], oacc[i]);
            }
            float inv = 1.f / l;
            uint32_t* op = (uint32_t*)&Obf[tid * AB_LD + head * 32];
            #pragma unroll
            for (int i = 0; i < 16; i++) {
                float2 r = unpack2(oacc[i]);
                op[i] = bf2pack(r.x * inv, r.y * inv);
            }
        }
    }

    // ---- stage Wout bf16 into Wq ----
    for (int i = tid; i < 1152; i += 256) {
        int n = i / 12, f = i - n * 12;
        cp16(Wq + n * AB_LD + f * 8, g_woutTb + n * 96 + f * 8);
    }
    cp_commit(); cp_wait<0>();
    __syncthreads();   // Wout + all Obf writes visible

    // ---- outproj mma: [224 x 96] = Obf @ WoutT ----
    float acc[7][3][4];
    #pragma unroll
    for (int mt = 0; mt < 7; mt++)
        #pragma unroll
        for (int nt = 0; nt < 3; nt++)
            #pragma unroll
            for (int i = 0; i < 4; i++) acc[mt][nt][i] = 0.f;
    #pragma unroll
    for (int ks = 0; ks < 6; ks++) {
        uint32_t bf[3][2];
        #pragma unroll
        for (int nt = 0; nt < 3; nt++)
            ldsm2(bf[nt], bW + (unsigned)(nt * 8 * AB_LD * 2 + ks * 32));
        #pragma unroll
        for (int mt = 0; mt < 7; mt++) {
            uint32_t af[4];
            ldsm4(af, aObf + (unsigned)(mt * 16 * AB_LD * 2 + ks * 32));
            #pragma unroll
            for (int nt = 0; nt < 3; nt++)
                mma_bf16(acc[mt][nt], af, bf[nt]);
        }
    }

    // ---- epilogue: +bias, +residual(g_xT), emit g_h1, LN2 stats ----
    #pragma unroll
    for (int mt = 0; mt < 7; mt++) {
        int r1 = wm * 112 + mt * 16 + g;
        int r2 = r1 + 8;
        float s1 = 0.f, q1 = 0.f, s2 = 0.f, q2 = 0.f;
        int t1 = ssrow[r1];
        int t2 = (r2 < 216) ? ssrow[r2] : 0;
        #pragma unroll
        for (int nt = 0; nt < 3; nt++) {
            int c = wn * 24 + nt * 8 + 2 * tq;
            float b0 = bout[c], b1v = bout[c + 1];
            {
                float2 xr = *(const float2*)&g_xT[(long)t1 * 96 + c];
                float v0 = acc[mt][nt][0] + b0 + xr.x;
                float v1 = acc[mt][nt][1] + b1v + xr.y;
                *(float2*)&g_h1[(long)t1 * 96 + c] = make_float2(v0, v1);
                acc[mt][nt][0] = v0; acc[mt][nt][1] = v1;
                s1 += v0 + v1; q1 += v0 * v0 + v1 * v1;
            }
            if (r2 < 216) {
                float2 xr = *(const float2*)&g_xT[(long)t2 * 96 + c];
                float v2 = acc[mt][nt][2] + b0 + xr.x;
                float v3 = acc[mt][nt][3] + b1v + xr.y;
                *(float2*)&g_h1[(long)t2 * 96 + c] = make_float2(v2, v3);
                acc[mt][nt][2] = v2; acc[mt][nt][3] = v3;
                s2 += v2 + v3; q2 += v2 * v2 + v3 * v3;
            }
        }
        s1 += __shfl_xor_sync(~0u, s1, 1); q1 += __shfl_xor_sync(~0u, q1, 1);
        s1 += __shfl_xor_sync(~0u, s1, 2); q1 += __shfl_xor_sync(~0u, q1, 2);
        s2 += __shfl_xor_sync(~0u, s2, 1); q2 += __shfl_xor_sync(~0u, q2, 1);
        s2 += __shfl_xor_sync(~0u, s2, 2); q2 += __shfl_xor_sync(~0u, q2, 2);
        if (tq == 0) {
            atomicAdd(&ssum[r1], s1); atomicAdd(&ssq[r1], q1);
            if (r2 < 216) { atomicAdd(&ssum[r2], s2); atomicAdd(&ssq[r2], q2); }
        }
    }
    __syncthreads();
    if (tid < 216) {
        float mu  = ssum[tid] * (1.f / 96.f);
        float var = fmaxf(ssq[tid] * (1.f / 96.f) - mu * mu, 0.f);
        smu[tid] = mu;
        srs[tid] = rsqrtf(var + 1e-5f);
    }
    __syncthreads();
    #pragma unroll
    for (int mt = 0; mt < 7; mt++) {
        int r1 = wm * 112 + mt * 16 + g;
        int r2 = r1 + 8;
        float mu1 = smu[r1], rs1 = srs[r1];
        float mu2 = (r2 < 216) ? smu[r2] : 0.f, rs2 = (r2 < 216) ? srs[r2] : 0.f;
        int t1 = ssrow[r1];
        int t2 = (r2 < 216) ? ssrow[r2] : 0;
        #pragma unroll
        for (int nt = 0; nt < 3; nt++) {
            int c = wn * 24 + nt * 8 + 2 * tq;
            float g0 = l2g[c], g1 = l2g[c + 1];
            float bb0 = l2b[c], bb1 = l2b[c + 1];
            {
                float n0 = (acc[mt][nt][0] - mu1) * rs1 * g0 + bb0;
                float n1 = (acc[mt][nt][1] - mu1) * rs1 * g1 + bb1;
                *(float2*)&g_hn[(long)t1 * 96 + c] = make_float2(n0, n1);
            }
            if (r2 < 216) {
                float n2 = (acc[mt][nt][2] - mu2) * rs2 * g0 + bb0;
                float n3 = (acc[mt][nt][3] - mu2) * rs2 * g1 + bb1;
                *(float2*)&g_hn[(long)t2 * 96 + c] = make_float2(n2, n3);
            }
        }
    }
}

// ---------------- K5: fused MLP, single-stage phases, BM=64 ----------------
#define K5_SMEM ((64 * 100 * 2 + 96 * 100) * 4)   // 89600
__global__ __launch_bounds__(256, 2) void k5_mlp(const float* __restrict__ b1,
                                                 const float* __restrict__ b2,
                                                 float* __restrict__ out) {
    extern __shared__ float sm[];
    float* As = sm;            // [64][100]
    float* Hs = sm + 6400;     // [64][100]
    float* Bs = sm + 12800;    // [96][100]
    int tid = threadIdx.x, warp = tid >> 5, lane = tid & 31;
    int wm = warp & 1, wn = warp >> 1;
    int g = lane >> 2, tq = lane & 3;
    long row0 = (long)blockIdx.x * 64;

    auto stageB = [&](const float* src, long rowStride) {
        #pragma unroll
        for (int i = 0; i < 9; i++) {
            int idx = tid + i * 256;
            int n = idx / 24, f = idx - n * 24;
            cp16(&Bs[n * 100 + f * 4], src + n * rowStride + f * 4);
        }
        cp_commit();
    };

    #pragma unroll
    for (int i = 0; i < 6; i++) {
        int idx = tid + i * 256;
        int r = idx / 24, f = idx - r * 24;
        cp16(&As[r * 100 + f * 4], &g_hn[(row0 + r) * 96 + f * 4]);
    }
    stageB(g_w1T, 96);
    cp_wait<0>();
    __syncthreads();

    int mi = lane >> 3, rr = lane & 7;
    unsigned aF = sptr(&As[(wm * 32 + rr + (mi & 1) * 8) * 100 + (mi >> 1) * 4]);
    unsigned aH = sptr(&Hs[(wm * 32 + rr + (mi & 1) * 8) * 100 + (mi >> 1) * 4]);
    unsigned bAddr = sptr(&Bs[(wn * 24 + rr) * 100 + ((lane >> 3) & 1) * 4]);

    float accO[2][3][4];
    #pragma unroll
    for (int mt = 0; mt < 2; mt++)
        #pragma unroll
        for (int nt = 0; nt < 3; nt++)
            #pragma unroll
            for (int i = 0; i < 4; i++) accO[mt][nt][i] = 0.f;

    for (int c = 0; c < 4; c++) {
        float acc1[2][3][4];
        #pragma unroll
        for (int mt = 0; mt < 2; mt++)
            #pragma unroll
            for (int nt = 0; nt < 3; nt++)
                #pragma unroll
                for (int i = 0; i < 4; i++) acc1[mt][nt][i] = 0.f;
        #pragma unroll
        for (int ks = 0; ks < 12; ks++) {
            int kb = ks * 8;
            float af[2][4];
            #pragma unroll
            for (int mt = 0; mt < 2; mt++)
                ldsm4(af[mt], aF + (unsigned)((mt * 16 * 100 + kb) * 4));
            float bf[3][2];
            #pragma unroll
            for (int nt = 0; nt < 3; nt++)
                ldsm2(bf[nt], bAddr + (unsigned)((nt * 8 * 100 + kb) * 4));
            #pragma unroll
            for (int mt = 0; mt < 2; mt++)
                #pragma unroll
                for (int nt = 0; nt < 3; nt++)
                    mma_tf32(acc1[mt][nt], af[mt], bf[nt]);
        }
        #pragma unroll
        for (int mt = 0; mt < 2; mt++) {
            int r = wm * 32 + mt * 16 + g;
            #pragma unroll
            for (int nt = 0; nt < 3; nt++) {
                int cl = wn * 24 + nt * 8 + 2 * tq;
                float b0 = b1[c * 96 + cl], bv = b1[c * 96 + cl + 1];
                Hs[r * 100 + cl]           = gelu_exact(acc1[mt][nt][0] + b0);
                Hs[r * 100 + cl + 1]       = gelu_exact(acc1[mt][nt][1] + bv);
                Hs[(r + 8) * 100 + cl]     = gelu_exact(acc1[mt][nt][2] + b0);
                Hs[(r + 8) * 100 + cl + 1] = gelu_exact(acc1[mt][nt][3] + bv);
            }
        }
        __syncthreads();
        stageB(g_w2T + c * 96, 384);
        cp_wait<0>();
        __syncthreads();
        #pragma unroll
        for (int ks = 0; ks < 12; ks++) {
            int kb = ks * 8;
            float af[2][4];
            #pragma unroll
            for (int mt = 0; mt < 2; mt++)
                ldsm4(af[mt], aH + (unsigned)((mt * 16 * 100 + kb) * 4));
            float bf[3][2];
            #pragma unroll
            for (int nt = 0; nt < 3; nt++)
                ldsm2(bf[nt], bAddr + (unsigned)((nt * 8 * 100 + kb) * 4));
            #pragma unroll
            for (int mt = 0; mt < 2; mt++)
                #pragma unroll
                for (int nt = 0; nt < 3; nt++)
                    mma_tf32(accO[mt][nt], af[mt], bf[nt]);
        }
        if (c < 3) {
            __syncthreads();
            stageB(g_w1T + (long)(c + 1) * 96 * 96, 96);
            cp_wait<0>();
            __syncthreads();
        }
    }

    __syncthreads();
    #pragma unroll
    for (int mt = 0; mt < 2; mt++) {
        int r = wm * 32 + mt * 16 + g;
        #pragma unroll
        for (int nt = 0; nt < 3; nt++) {
            int cl = wn * 24 + nt * 8 + 2 * tq;
            float b0 = b2[cl], bv = b2[cl + 1];
            As[r * 100 + cl]           = accO[mt][nt][0] + b0;
            As[r * 100 + cl + 1]       = accO[mt][nt][1] + bv;
            As[(r + 8) * 100 + cl]     = accO[mt][nt][2] + b0;
            As[(r + 8) * 100 + cl + 1] = accO[mt][nt][3] + bv;
        }
    }
    __syncthreads();
    for (int i = tid; i < 64 * 96; i += 256) {
        int r = i / 96, c = i - r * 96;
        As[r * 100 + c] += g_h1[(row0 + r) * 96 + c];
    }
    __syncthreads();
    for (int i = tid; i < 64 * 96; i += 256) {
        int c = i >> 6, r = i & 63;
        out[(long)c * S_TOK + row0 + r] = As[r * 100 + c];
    }
}

// ---------------- launch ----------------
extern "C" void kernel_launch(void* const* d_in, const int* in_sizes, int n_in,
                              void* d_out, int out_size) {
    const float* x    = (const float*)d_in[0];
    const float* l1g  = (const float*)d_in[1];
    const float* l1b  = (const float*)d_in[2];
    const float* wqkv = (const float*)d_in[3];
    const float* wout = (const float*)d_in[4];
    const float* bout = (const float*)d_in[5];
    const float* l2g  = (const float*)d_in[6];
    const float* l2b  = (const float*)d_in[7];
    const float* w1   = (const float*)d_in[8];
    const float* b1   = (const float*)d_in[9];
    const float* w2   = (const float*)d_in[10];
    const float* b2   = (const float*)d_in[11];
    float* out = (float*)d_out;

    cudaFuncSetAttribute(k34_attn, cudaFuncAttributeMaxDynamicSharedMemorySize, K34_SMEM);
    cudaFuncSetAttribute(k5_mlp,   cudaFuncAttributeMaxDynamicSharedMemorySize, K5_SMEM);

    float *p_w1T, *p_w2T;
    cudaGetSymbolAddress((void**)&p_w1T, g_w1T);
    cudaGetSymbolAddress((void**)&p_w2T, g_w2T);

    dim3 tb(32, 8);
    k0q_wqkvb<<<108, 256>>>(wqkv);
    k0_transpose<<<dim3(12, 3), tb>>>(w1, p_w1T, 96, 384);
    k0_transpose<<<dim3(3, 12), tb>>>(w2, p_w2T, 384, 96);
    k0b_woutb<<<36, 256>>>(wout);

    k1_ln1<<<S_TOK / 64, 256>>>(x, l1g, l1b);
    k34_attn<<<512, 256, K34_SMEM>>>(bout, l2g, l2b);
    k5_mlp<<<S_TOK / 64, 256, K5_SMEM>>>(b1, b2, out);
}

// round 10
// speedup vs baseline: 1.2566x; 1.1073x over previous
#include <cuda_runtime.h>
#include <cuda_bf16.h>
#include <math.h>
#include <stdint.h>

#define S_TOK 110592   // 48*48*48

typedef unsigned long long ull;

// ---------------- scratch (device globals; no allocation) ----------------
__device__ unsigned short g_xwb[S_TOK * 96];  // LN1'd activations, window-ordered, bf16
__device__ float g_xT  [S_TOK * 96];   // raw x, token-major (fp32: carries main signal)
__device__ float g_h1  [S_TOK * 96];   // residual-1, token-major (fp32)
__device__ unsigned short g_hnb[S_TOK * 96];  // LN2 output, token-major, bf16
__device__ unsigned short g_wqkvTb[288 * 96]; // bf16 [n][k]
__device__ unsigned short g_woutTb[96 * 96];  // bf16 [n][k]
__device__ unsigned short g_w1Tb  [384 * 96]; // bf16 [n][k]
__device__ unsigned short g_w2Tb  [96 * 384]; // bf16 [n][k]

// ---------------- helpers ----------------
__device__ __forceinline__ float gelu_exact(float v) {
    return 0.5f * v * (1.0f + erff(v * 0.70710678118654752440f));
}
__device__ __forceinline__ void mma_bf16(float* d, const uint32_t* A, const uint32_t* B) {
    asm("mma.sync.aligned.m16n8k16.row.col.f32.bf16.bf16.f32 "
        "{%0,%1,%2,%3}, {%4,%5,%6,%7}, {%8,%9}, {%0,%1,%2,%3};"
        : "+f"(d[0]), "+f"(d[1]), "+f"(d[2]), "+f"(d[3])
        : "r"(A[0]), "r"(A[1]), "r"(A[2]), "r"(A[3]), "r"(B[0]), "r"(B[1]));
}
__device__ __forceinline__ unsigned sptr(const void* p) {
    return (unsigned)__cvta_generic_to_shared(p);
}
__device__ __forceinline__ void ldsm4(void* r, unsigned a) {
    uint32_t* R = (uint32_t*)r;
    asm volatile("ldmatrix.sync.aligned.m8n8.x4.shared.b16 {%0,%1,%2,%3}, [%4];"
        : "=r"(R[0]), "=r"(R[1]), "=r"(R[2]), "=r"(R[3]) : "r"(a));
}
__device__ __forceinline__ void ldsm2(void* r, unsigned a) {
    uint32_t* R = (uint32_t*)r;
    asm volatile("ldmatrix.sync.aligned.m8n8.x2.shared.b16 {%0,%1}, [%2];"
        : "=r"(R[0]), "=r"(R[1]) : "r"(a));
}
__device__ __forceinline__ ull fma2(ull a, ull b, ull c) {
    ull d; asm("fma.rn.f32x2 %0, %1, %2, %3;" : "=l"(d) : "l"(a), "l"(b), "l"(c));
    return d;
}
__device__ __forceinline__ ull pack2(float lo, float hi) {
    ull d; asm("mov.b64 %0, {%1, %2};" : "=l"(d) : "f"(lo), "f"(hi));
    return d;
}
__device__ __forceinline__ float2 unpack2(ull v) {
    float lo, hi; asm("mov.b64 {%0, %1}, %2;" : "=f"(lo), "=f"(hi) : "l"(v));
    return make_float2(lo, hi);
}
__device__ __forceinline__ uint32_t bf2pack(float lo, float hi) {
    uint32_t r; asm("cvt.rn.bf16x2.f32 %0, %1, %2;" : "=r"(r) : "f"(hi), "f"(lo));
    return r;
}
__device__ __forceinline__ void cp16(void* dst, const void* src) {
    unsigned d = (unsigned)__cvta_generic_to_shared(dst);
    asm volatile("cp.async.cg.shared.global [%0], [%1], 16;\n" :: "r"(d), "l"(src));
}
__device__ __forceinline__ void cp_commit() { asm volatile("cp.async.commit_group;\n"); }
template<int N> __device__ __forceinline__ void cp_wait() {
    asm volatile("cp.async.wait_group %0;\n" :: "n"(N));
}
__device__ __forceinline__ int wt_to_s(int gr) {
    int wiw = gr / 216, ti = gr - wiw * 216;
    int nd = wiw >> 6, nh = (wiw >> 3) & 7, nw = wiw & 7;
    int wd = ti / 36, wh = (ti / 6) % 6, ww = ti % 6;
    return ((nd * 6 + wd) * 48 + (nh * 6 + wh)) * 48 + (nw * 6 + ww);
}

// ---------------- K0: all weight->bf16 transposed conversions, one kernel ----------------
__global__ void k0_prep(const float* __restrict__ wqkv, const float* __restrict__ wout,
                        const float* __restrict__ w1,   const float* __restrict__ w2) {
    int job = blockIdx.y;
    int i = blockIdx.x * 256 + threadIdx.x;
    if (job == 0) {
        if (i < 288 * 96) {
            int n = i / 96, k = i - n * 96;
            __nv_bfloat16 b = __float2bfloat16(wqkv[k * 288 + n]);
            g_wqkvTb[i] = *(unsigned short*)&b;
        }
    } else if (job == 1) {
        if (i < 96 * 96) {
            int n = i / 96, k = i - n * 96;
            __nv_bfloat16 b = __float2bfloat16(wout[k * 96 + n]);
            g_woutTb[i] = *(unsigned short*)&b;
        }
    } else if (job == 2) {
        if (i < 384 * 96) {
            int n = i / 96, k = i - n * 96;
            __nv_bfloat16 b = __float2bfloat16(w1[k * 384 + n]);
            g_w1Tb[i] = *(unsigned short*)&b;
        }
    } else {
        if (i < 96 * 384) {
            int n = i / 384, k = i - n * 384;
            __nv_bfloat16 b = __float2bfloat16(w2[k * 96 + n]);
            g_w2Tb[i] = *(unsigned short*)&b;
        }
    }
}

// ---------------- K1: LN1 + window partition (bf16) + transpose ----------------
__global__ __launch_bounds__(256) void k1_ln1(const float* __restrict__ x,
                                              const float* __restrict__ gw,
                                              const float* __restrict__ gb) {
    __shared__ float xs[64 * 97];
    __shared__ float smu[64], srs[64];
    __shared__ int srow[64];
    __shared__ float sg[96], sb[96];
    int tid = threadIdx.x;
    int s0 = blockIdx.x * 64;
    if (tid < 96) { sg[tid] = gw[tid]; sb[tid] = gb[tid]; }
    #pragma unroll
    for (int it = 0; it < 24; it++) {
        int i = it * 256 + tid;
        int c = i >> 6, t = i & 63;
        xs[t * 97 + c] = x[(long)c * S_TOK + s0 + t];
    }
    if (tid < 64) {
        int s = s0 + tid;
        int w = s % 48, h = (s / 48) % 48, d = s / 2304;
        int wi = ((d / 6) * 8 + (h / 6)) * 8 + (w / 6);
        int ti = ((d % 6) * 6 + (h % 6)) * 6 + (w % 6);
        srow[tid] = wi * 216 + ti;
    }
    __syncthreads();
    {
        int t = tid >> 2, p = tid & 3;
        float sum = 0.f, sq = 0.f;
        const float* row = &xs[t * 97 + p * 24];
        #pragma unroll
        for (int j = 0; j < 24; j++) { float v = row[j]; sum += v; sq += v * v; }
        sum += __shfl_xor_sync(~0u, sum, 1); sq += __shfl_xor_sync(~0u, sq, 1);
        sum += __shfl_xor_sync(~0u, sum, 2); sq += __shfl_xor_sync(~0u, sq, 2);
        if (p == 0) {
            float mu  = sum * (1.f / 96.f);
            float var = fmaxf(sq * (1.f / 96.f) - mu * mu, 0.f);
            smu[t] = mu;
            srs[t] = rsqrtf(var + 1e-5f);
        }
    }
    __syncthreads();
    #pragma unroll
    for (int it = 0; it < 24; it++) {
        int i = it * 256 + tid;
        int t = i / 96, c = i - t * 96;
        g_xT[((long)(s0 + t)) * 96 + c] = xs[t * 97 + c];
    }
    #pragma unroll
    for (int it = 0; it < 12; it++) {
        int i = it * 256 + tid;
        int t = i / 48, c2 = (i - t * 48) * 2;
        float v0 = (xs[t * 97 + c2]     - smu[t]) * srs[t] * sg[c2]     + sb[c2];
        float v1 = (xs[t * 97 + c2 + 1] - smu[t]) * srs[t] * sg[c2 + 1] + sb[c2 + 1];
        ((uint32_t*)g_xwb)[(long)srow[t] * 48 + c2 / 2] = bf2pack(v0, v1);
    }
}

// ---------------- K34: LN1'd-x -> QKV -> attention -> outproj -> res -> LN2 ----------------
#define AB_LD 104
#define K34_SMEM 197824
__global__ __launch_bounds__(256, 1) void k34_attn(const float* __restrict__ bout,
                                                   const float* __restrict__ l2g,
                                                   const float* __restrict__ l2b) {
    extern __shared__ char smc[];
    unsigned short* Asb = (unsigned short*)smc;
    unsigned short* Obf = (unsigned short*)(smc + 46592);
    unsigned short* Wq  = (unsigned short*)(smc + 93184);
    float* Qs = (float*)(smc + 113152);   // [216][34]
    float* Ks = (float*)(smc + 142528);   // [216][32]
    float* Vs = (float*)(smc + 170176);   // [216][32]
    __shared__ float ssum[224], ssq[224], smu[224], srs[224];
    __shared__ int ssrow[224];

    int wi = blockIdx.x, tid = threadIdx.x;
    int warp = tid >> 5, lane = tid & 31;
    int wm = warp & 1, wn = warp >> 1;
    int g = lane >> 2, tq = lane & 3;
    int rr = lane & 7;

    if (tid < 224) { ssum[tid] = 0.f; ssq[tid] = 0.f; }
    if (tid < 216) ssrow[tid] = wt_to_s(wi * 216 + tid);
    for (int i = tid; i < 416; i += 256) {
        ((uint32_t*)(Asb + 216 * AB_LD))[i] = 0;
        ((uint32_t*)(Obf + 216 * AB_LD))[i] = 0;
    }

    const unsigned short* xsrc = g_xwb + (long)wi * 216 * 96;
    for (int i = tid; i < 2592; i += 256) {
        int r = i / 12, f = i - r * 12;
        cp16(Asb + r * AB_LD + f * 8, xsrc + r * 96 + f * 8);
    }
    cp_commit();

    unsigned aAsb = sptr(Asb) +
        (unsigned)(((wm * 112 + rr + ((lane >> 3) & 1) * 8) * AB_LD +
                    ((lane >> 4) & 1) * 8) * 2);
    unsigned aObf = sptr(Obf) +
        (unsigned)(((wm * 112 + rr + ((lane >> 3) & 1) * 8) * AB_LD +
                    ((lane >> 4) & 1) * 8) * 2);
    unsigned bW = sptr(Wq) +
        (unsigned)(((wn * 24 + rr) * AB_LD + ((lane >> 3) & 1) * 8) * 2);

    for (int head = 0; head < 3; head++) {
        for (int i = tid; i < 1152; i += 256) {
            int n = i / 12, f = i - n * 12;
            int src = (n < 32) ? (head * 32 + n)
                    : (n < 64) ? (96 + head * 32 + n - 32)
                               : (192 + head * 32 + n - 64);
            cp16(Wq + n * AB_LD + f * 8, g_wqkvTb + src * 96 + f * 8);
        }
        cp_commit(); cp_wait<0>();
        __syncthreads();

        float acc[7][3][4];
        #pragma unroll
        for (int mt = 0; mt < 7; mt++)
            #pragma unroll
            for (int nt = 0; nt < 3; nt++)
                #pragma unroll
                for (int i = 0; i < 4; i++) acc[mt][nt][i] = 0.f;
        #pragma unroll
        for (int ks = 0; ks < 6; ks++) {
            uint32_t bf[3][2];
            #pragma unroll
            for (int nt = 0; nt < 3; nt++)
                ldsm2(bf[nt], bW + (unsigned)(nt * 8 * AB_LD * 2 + ks * 32));
            #pragma unroll
            for (int mt = 0; mt < 7; mt++) {
                uint32_t af[4];
                ldsm4(af, aAsb + (unsigned)(mt * 16 * AB_LD * 2 + ks * 32));
                #pragma unroll
                for (int nt = 0; nt < 3; nt++)
                    mma_bf16(acc[mt][nt], af, bf[nt]);
            }
        }
        #pragma unroll
        for (int mt = 0; mt < 7; mt++) {
            int r1 = wm * 112 + mt * 16 + g;
            int r2 = r1 + 8;
            #pragma unroll
            for (int nt = 0; nt < 3; nt++) {
                int c = wn * 24 + nt * 8 + 2 * tq;
                float2 v1 = make_float2(acc[mt][nt][0], acc[mt][nt][1]);
                float2 v2 = make_float2(acc[mt][nt][2], acc[mt][nt][3]);
                if (c < 32) {
                    *(float2*)&Qs[r1 * 34 + c] = v1;
                    if (r2 < 216) *(float2*)&Qs[r2 * 34 + c] = v2;
                } else if (c < 64) {
                    *(float2*)&Ks[r1 * 32 + c - 32] = v1;
                    if (r2 < 216) *(float2*)&Ks[r2 * 32 + c - 32] = v2;
                } else {
                    *(float2*)&Vs[r1 * 32 + c - 64] = v1;
                    if (r2 < 216) *(float2*)&Vs[r2 * 32 + c - 64] = v2;
                }
            }
        }
        __syncthreads();

        if (tid < 216) {
            ull qp[16];
            const ull* q8 = (const ull*)&Qs[tid * 34];
            #pragma unroll
            for (int i = 0; i < 16; i++) qp[i] = q8[i];
            ull z = pack2(0.f, 0.f);
            ull oacc[16];
            #pragma unroll
            for (int i = 0; i < 16; i++) oacc[i] = z;
            float l = 0.f;
            for (int j = 0; j < 216; j += 2) {
                const ull* kj0 = (const ull*)&Ks[j * 32];
                const ull* kj1 = (const ull*)&Ks[(j + 1) * 32];
                ull s0a = z, s1a = z, s0b = z, s1b = z;
                #pragma unroll
                for (int i = 0; i < 8; i++) {
                    s0a = fma2(qp[2 * i],     kj0[2 * i],     s0a);
                    s1a = fma2(qp[2 * i + 1], kj0[2 * i + 1], s1a);
                    s0b = fma2(qp[2 * i],     kj1[2 * i],     s0b);
                    s1b = fma2(qp[2 * i + 1], kj1[2 * i + 1], s1b);
                }
                float2 f0a = unpack2(s0a), f1a = unpack2(s1a);
                float2 f0b = unpack2(s0b), f1b = unpack2(s1b);
                float sa = ((f0a.x + f0a.y) + (f1a.x + f1a.y)) * 0.17677669529663687f;
                float sb2 = ((f0b.x + f0b.y) + (f1b.x + f1b.y)) * 0.17677669529663687f;
                float pa = __expf(sa);   // tiny scores; softmax w/o max-sub exact
                float pb = __expf(sb2);
                l += pa + pb;
                ull ppa = pack2(pa, pa), ppb = pack2(pb, pb);
                const ull* vj0 = (const ull*)&Vs[j * 32];
                const ull* vj1 = (const ull*)&Vs[(j + 1) * 32];
                #pragma unroll
                for (int i = 0; i < 16; i++)
                    oacc[i] = fma2(ppb, vj1[i], fma2(ppa, vj0[i], oacc[i]));
            }
            float inv = 1.f / l;
            uint32_t* op = (uint32_t*)&Obf[tid * AB_LD + head * 32];
            #pragma unroll
            for (int i = 0; i < 16; i++) {
                float2 r = unpack2(oacc[i]);
                op[i] = bf2pack(r.x * inv, r.y * inv);
            }
        }
    }

    for (int i = tid; i < 1152; i += 256) {
        int n = i / 12, f = i - n * 12;
        cp16(Wq + n * AB_LD + f * 8, g_woutTb + n * 96 + f * 8);
    }
    cp_commit(); cp_wait<0>();
    __syncthreads();

    float acc[7][3][4];
    #pragma unroll
    for (int mt = 0; mt < 7; mt++)
        #pragma unroll
        for (int nt = 0; nt < 3; nt++)
            #pragma unroll
            for (int i = 0; i < 4; i++) acc[mt][nt][i] = 0.f;
    #pragma unroll
    for (int ks = 0; ks < 6; ks++) {
        uint32_t bf[3][2];
        #pragma unroll
        for (int nt = 0; nt < 3; nt++)
            ldsm2(bf[nt], bW + (unsigned)(nt * 8 * AB_LD * 2 + ks * 32));
        #pragma unroll
        for (int mt = 0; mt < 7; mt++) {
            uint32_t af[4];
            ldsm4(af, aObf + (unsigned)(mt * 16 * AB_LD * 2 + ks * 32));
            #pragma unroll
            for (int nt = 0; nt < 3; nt++)
                mma_bf16(acc[mt][nt], af, bf[nt]);
        }
    }

    #pragma unroll
    for (int mt = 0; mt < 7; mt++) {
        int r1 = wm * 112 + mt * 16 + g;
        int r2 = r1 + 8;
        float s1 = 0.f, q1 = 0.f, s2 = 0.f, q2 = 0.f;
        int t1 = ssrow[r1];
        int t2 = (r2 < 216) ? ssrow[r2] : 0;
        #pragma unroll
        for (int nt = 0; nt < 3; nt++) {
            int c = wn * 24 + nt * 8 + 2 * tq;
            float b0 = bout[c], b1v = bout[c + 1];
            {
                float2 xr = *(const float2*)&g_xT[(long)t1 * 96 + c];
                float v0 = acc[mt][nt][0] + b0 + xr.x;
                float v1 = acc[mt][nt][1] + b1v + xr.y;
                *(float2*)&g_h1[(long)t1 * 96 + c] = make_float2(v0, v1);
                acc[mt][nt][0] = v0; acc[mt][nt][1] = v1;
                s1 += v0 + v1; q1 += v0 * v0 + v1 * v1;
            }
            if (r2 < 216) {
                float2 xr = *(const float2*)&g_xT[(long)t2 * 96 + c];
                float v2 = acc[mt][nt][2] + b0 + xr.x;
                float v3 = acc[mt][nt][3] + b1v + xr.y;
                *(float2*)&g_h1[(long)t2 * 96 + c] = make_float2(v2, v3);
                acc[mt][nt][2] = v2; acc[mt][nt][3] = v3;
                s2 += v2 + v3; q2 += v2 * v2 + v3 * v3;
            }
        }
        s1 += __shfl_xor_sync(~0u, s1, 1); q1 += __shfl_xor_sync(~0u, q1, 1);
        s1 += __shfl_xor_sync(~0u, s1, 2); q1 += __shfl_xor_sync(~0u, q1, 2);
        s2 += __shfl_xor_sync(~0u, s2, 1); q2 += __shfl_xor_sync(~0u, q2, 1);
        s2 += __shfl_xor_sync(~0u, s2, 2); q2 += __shfl_xor_sync(~0u, q2, 2);
        if (tq == 0) {
            atomicAdd(&ssum[r1], s1); atomicAdd(&ssq[r1], q1);
            if (r2 < 216) { atomicAdd(&ssum[r2], s2); atomicAdd(&ssq[r2], q2); }
        }
    }
    __syncthreads();
    if (tid < 216) {
        float mu  = ssum[tid] * (1.f / 96.f);
        float var = fmaxf(ssq[tid] * (1.f / 96.f) - mu * mu, 0.f);
        smu[tid] = mu;
        srs[tid] = rsqrtf(var + 1e-5f);
    }
    __syncthreads();
    #pragma unroll
    for (int mt = 0; mt < 7; mt++) {
        int r1 = wm * 112 + mt * 16 + g;
        int r2 = r1 + 8;
        float mu1 = smu[r1], rs1 = srs[r1];
        float mu2 = (r2 < 216) ? smu[r2] : 0.f, rs2 = (r2 < 216) ? srs[r2] : 0.f;
        int t1 = ssrow[r1];
        int t2 = (r2 < 216) ? ssrow[r2] : 0;
        #pragma unroll
        for (int nt = 0; nt < 3; nt++) {
            int c = wn * 24 + nt * 8 + 2 * tq;
            float g0 = l2g[c], g1 = l2g[c + 1];
            float bb0 = l2b[c], bb1 = l2b[c + 1];
            {
                float n0 = (acc[mt][nt][0] - mu1) * rs1 * g0 + bb0;
                float n1 = (acc[mt][nt][1] - mu1) * rs1 * g1 + bb1;
                ((uint32_t*)g_hnb)[(long)t1 * 48 + c / 2] = bf2pack(n0, n1);
            }
            if (r2 < 216) {
                float n2 = (acc[mt][nt][2] - mu2) * rs2 * g0 + bb0;
                float n3 = (acc[mt][nt][3] - mu2) * rs2 * g1 + bb1;
                ((uint32_t*)g_hnb)[(long)t2 * 48 + c / 2] = bf2pack(n2, n3);
            }
        }
    }
}

// ---------------- K5: fused MLP, all-bf16 mma, BM=64 ----------------
// smem: Asb[64][104]bf16 @0, Hsb[64][104]bf16 @13312, Bsb[96][104]bf16 @26624
// Cs fp32 [64][100] overlays @0 (post-mma only)
#define K5_SMEM 46592
__global__ __launch_bounds__(256, 2) void k5_mlp(const float* __restrict__ b1,
                                                 const float* __restrict__ b2,
                                                 float* __restrict__ out) {
    extern __shared__ char smc[];
    unsigned short* Asb = (unsigned short*)smc;
    unsigned short* Hsb = (unsigned short*)(smc + 13312);
    unsigned short* Bsb = (unsigned short*)(smc + 26624);
    float* Cs = (float*)smc;
    int tid = threadIdx.x, warp = tid >> 5, lane = tid & 31;
    int wm = warp & 1, wn = warp >> 1;
    int g = lane >> 2, tq = lane & 3, rr = lane & 7;
    long row0 = (long)blockIdx.x * 64;

    auto stageB = [&](const unsigned short* src, int rowStride) {
        #pragma unroll
        for (int i = 0; i < 5; i++) {
            int idx = tid + i * 256;
            if (idx < 1152) {
                int n = idx / 12, f = idx - n * 12;
                cp16(Bsb + n * 104 + f * 8, src + (long)n * rowStride + f * 8);
            }
        }
        cp_commit();
    };

    // A: 64 rows x 12 chunks = 768
    #pragma unroll
    for (int i = 0; i < 3; i++) {
        int idx = tid + i * 256;
        int r = idx / 12, f = idx - r * 12;
        cp16(Asb + r * 104 + f * 8, g_hnb + (row0 + r) * 96 + f * 8);
    }
    stageB(g_w1Tb, 96);
    cp_wait<0>();
    __syncthreads();

    unsigned aA = sptr(Asb) +
        (unsigned)(((wm * 32 + rr + ((lane >> 3) & 1) * 8) * 104 + ((lane >> 4) & 1) * 8) * 2);
    unsigned aH = sptr(Hsb) +
        (unsigned)(((wm * 32 + rr + ((lane >> 3) & 1) * 8) * 104 + ((lane >> 4) & 1) * 8) * 2);
    unsigned bB = sptr(Bsb) +
        (unsigned)(((wn * 24 + rr) * 104 + ((lane >> 3) & 1) * 8) * 2);

    float accO[2][3][4];
    #pragma unroll
    for (int mt = 0; mt < 2; mt++)
        #pragma unroll
        for (int nt = 0; nt < 3; nt++)
            #pragma unroll
            for (int i = 0; i < 4; i++) accO[mt][nt][i] = 0.f;

    for (int c = 0; c < 4; c++) {
        // phase 1: hidden chunk = Asb @ W1_c^T
        float acc1[2][3][4];
        #pragma unroll
        for (int mt = 0; mt < 2; mt++)
            #pragma unroll
            for (int nt = 0; nt < 3; nt++)
                #pragma unroll
                for (int i = 0; i < 4; i++) acc1[mt][nt][i] = 0.f;
        #pragma unroll
        for (int ks = 0; ks < 6; ks++) {
            uint32_t bf[3][2];
            #pragma unroll
            for (int nt = 0; nt < 3; nt++)
                ldsm2(bf[nt], bB + (unsigned)(nt * 8 * 104 * 2 + ks * 32));
            #pragma unroll
            for (int mt = 0; mt < 2; mt++) {
                uint32_t af[4];
                ldsm4(af, aA + (unsigned)(mt * 16 * 104 * 2 + ks * 32));
                #pragma unroll
                for (int nt = 0; nt < 3; nt++)
                    mma_bf16(acc1[mt][nt], af, bf[nt]);
            }
        }
        // gelu -> Hsb (bf16 pairs)
        #pragma unroll
        for (int mt = 0; mt < 2; mt++) {
            int r = wm * 32 + mt * 16 + g;
            #pragma unroll
            for (int nt = 0; nt < 3; nt++) {
                int cl = wn * 24 + nt * 8 + 2 * tq;
                float b0 = b1[c * 96 + cl], bv = b1[c * 96 + cl + 1];
                ((uint32_t*)Hsb)[r * 52 + cl / 2] =
                    bf2pack(gelu_exact(acc1[mt][nt][0] + b0), gelu_exact(acc1[mt][nt][1] + bv));
                ((uint32_t*)Hsb)[(r + 8) * 52 + cl / 2] =
                    bf2pack(gelu_exact(acc1[mt][nt][2] + b0), gelu_exact(acc1[mt][nt][3] + bv));
            }
        }
        __syncthreads();
        stageB(g_w2Tb + c * 96, 384);
        cp_wait<0>();
        __syncthreads();
        // phase 2: accO += Hsb @ W2_c^T
        #pragma unroll
        for (int ks = 0; ks < 6; ks++) {
            uint32_t bf[3][2];
            #pragma unroll
            for (int nt = 0; nt < 3; nt++)
                ldsm2(bf[nt], bB + (unsigned)(nt * 8 * 104 * 2 + ks * 32));
            #pragma unroll
            for (int mt = 0; mt < 2; mt++) {
                uint32_t af[4];
                ldsm4(af, aH + (unsigned)(mt * 16 * 104 * 2 + ks * 32));
                #pragma unroll
                for (int nt = 0; nt < 3; nt++)
                    mma_bf16(accO[mt][nt], af, bf[nt]);
            }
        }
        if (c < 3) {
            __syncthreads();
            stageB(g_w1Tb + (long)(c + 1) * 96 * 96, 96);
            cp_wait<0>();
            __syncthreads();
        }
    }

    __syncthreads();   // all mma done; Cs may overlay Asb/Hsb
    #pragma unroll
    for (int mt = 0; mt < 2; mt++) {
        int r = wm * 32 + mt * 16 + g;
        #pragma unroll
        for (int nt = 0; nt < 3; nt++) {
            int cl = wn * 24 + nt * 8 + 2 * tq;
            float b0 = b2[cl], bv = b2[cl + 1];
            Cs[r * 100 + cl]           = accO[mt][nt][0] + b0;
            Cs[r * 100 + cl + 1]       = accO[mt][nt][1] + bv;
            Cs[(r + 8) * 100 + cl]     = accO[mt][nt][2] + b0;
            Cs[(r + 8) * 100 + cl + 1] = accO[mt][nt][3] + bv;
        }
    }
    __syncthreads();
    for (int i = tid; i < 64 * 96; i += 256) {
        int r = i / 96, c = i - r * 96;
        Cs[r * 100 + c] += g_h1[(row0 + r) * 96 + c];
    }
    __syncthreads();
    for (int i = tid; i < 64 * 96; i += 256) {
        int c = i >> 6, r = i & 63;
        out[(long)c * S_TOK + row0 + r] = Cs[r * 100 + c];
    }
}

// ---------------- launch ----------------
extern "C" void kernel_launch(void* const* d_in, const int* in_sizes, int n_in,
                              void* d_out, int out_size) {
    const float* x    = (const float*)d_in[0];
    const float* l1g  = (const float*)d_in[1];
    const float* l1b  = (const float*)d_in[2];
    const float* wqkv = (const float*)d_in[3];
    const float* wout = (const float*)d_in[4];
    const float* bout = (const float*)d_in[5];
    const float* l2g  = (const float*)d_in[6];
    const float* l2b  = (const float*)d_in[7];
    const float* w1   = (const float*)d_in[8];
    const float* b1   = (const float*)d_in[9];
    const float* w2   = (const float*)d_in[10];
    const float* b2   = (const float*)d_in[11];
    float* out = (float*)d_out;

    cudaFuncSetAttribute(k34_attn, cudaFuncAttributeMaxDynamicSharedMemorySize, K34_SMEM);
    cudaFuncSetAttribute(k5_mlp,   cudaFuncAttributeMaxDynamicSharedMemorySize, K5_SMEM);

    k0_prep<<<dim3(144, 4), 256>>>(wqkv, wout, w1, w2);
    k1_ln1<<<S_TOK / 64, 256>>>(x, l1g, l1b);
    k34_attn<<<512, 256, K34_SMEM>>>(bout, l2g, l2b);
    k5_mlp<<<S_TOK / 64, 256, K5_SMEM>>>(b1, b2, out);
}